// round 5
// baseline (speedup 1.0000x reference)
#include <cuda_runtime.h>
#include <cuda_bf16.h>
#include <cstdint>

#define BB 16
#define LL 512
#define DD 256
#define FF 256
#define MM 2048
#define EPSV 1e-5f

// ---------------- device scratch (16B aligned for cp.async/ldmatrix) --------
__device__ __align__(16) __nv_bfloat16 g_xhi[BB * LL * DD];
__device__ __align__(16) __nv_bfloat16 g_xlo[BB * LL * DD];
__device__ __align__(16) __nv_bfloat16 g_h1hi[BB * LL * FF];
__device__ __align__(16) __nv_bfloat16 g_h1lo[BB * LL * FF];
// weights staged as [kc=8][f=256][tap=3][d=32]  (196608 elems each)
__device__ __align__(16) __nv_bfloat16 g_B1h[8 * 256 * 3 * 32];
__device__ __align__(16) __nv_bfloat16 g_B1l[8 * 256 * 3 * 32];
__device__ __align__(16) __nv_bfloat16 g_B2h[8 * 256 * 3 * 32];
__device__ __align__(16) __nv_bfloat16 g_B2l[8 * 256 * 3 * 32];
__device__ int g_cs[BB * LL];

// ---------------- helpers ----------------
__device__ __forceinline__ uint32_t smem_u32(const void* p) {
    uint32_t a;
    asm("{ .reg .u64 t; cvta.to.shared.u64 t, %1; cvt.u32.u64 %0, t; }"
        : "=r"(a) : "l"(p));
    return a;
}

__device__ __forceinline__ void cp16(uint32_t dst, const void* src, int valid) {
    int sz = valid ? 16 : 0;
    asm volatile("cp.async.cg.shared.global [%0], [%1], %2, %3;"
                 :: "r"(dst), "l"(src), "n"(16), "r"(sz));
}
__device__ __forceinline__ void cp_commit() {
    asm volatile("cp.async.commit_group;" ::: "memory");
}
__device__ __forceinline__ void cp_wait1() {
    asm volatile("cp.async.wait_group 1;" ::: "memory");
}
__device__ __forceinline__ void cp_wait0() {
    asm volatile("cp.async.wait_group 0;" ::: "memory");
}

__device__ __forceinline__ void ldsm4(uint32_t* r, uint32_t addr) {
    asm volatile("ldmatrix.sync.aligned.m8n8.x4.shared.b16 {%0,%1,%2,%3}, [%4];"
                 : "=r"(r[0]), "=r"(r[1]), "=r"(r[2]), "=r"(r[3]) : "r"(addr));
}

__device__ __forceinline__ void mma16816(float* d, const uint32_t* a,
                                         const uint32_t* b) {
    asm volatile(
        "mma.sync.aligned.m16n8k16.row.col.f32.bf16.bf16.f32 "
        "{%0,%1,%2,%3}, {%4,%5,%6,%7}, {%8,%9}, {%0,%1,%2,%3};"
        : "+f"(d[0]), "+f"(d[1]), "+f"(d[2]), "+f"(d[3])
        : "r"(a[0]), "r"(a[1]), "r"(a[2]), "r"(a[3]), "r"(b[0]), "r"(b[1]));
}

// ---------------- prep: bf16 hi/lo splits (vectorized) ----------------
__global__ void prep_convert(const float* __restrict__ x,
                             const float* __restrict__ w1,
                             const float* __restrict__ w2) {
    int i4 = blockIdx.x * 256 + threadIdx.x;   // vec4 index
    if (i4 < BB * LL * DD / 4) {
        float4 v = reinterpret_cast<const float4*>(x)[i4];
        __nv_bfloat16 h[4], l[4];
        float vv[4] = {v.x, v.y, v.z, v.w};
#pragma unroll
        for (int j = 0; j < 4; j++) {
            h[j] = __float2bfloat16(vv[j]);
            l[j] = __float2bfloat16(vv[j] - __bfloat162float(h[j]));
        }
        reinterpret_cast<uint2*>(g_xhi)[i4] = *(uint2*)h;
        reinterpret_cast<uint2*>(g_xlo)[i4] = *(uint2*)l;
    }
    if (i4 < 8 * 256 * 3 * 32 / 4) {
        __nv_bfloat16 h1[4], l1[4], h2[4], l2[4];
#pragma unroll
        for (int j = 0; j < 4; j++) {
            int i = i4 * 4 + j;
            // dst layout [kc][f][tap][32d];  src w[f][d][tap], d = kc*32+d0
            int kc = i / 24576, r = i % 24576;
            int f = r / 96, r2 = r % 96;
            int tap = r2 / 32, d0 = r2 % 32;
            int d = kc * 32 + d0;
            float v1 = w1[f * 768 + d * 3 + tap];
            h1[j] = __float2bfloat16(v1);
            l1[j] = __float2bfloat16(v1 - __bfloat162float(h1[j]));
            float v2 = w2[f * 768 + d * 3 + tap];
            h2[j] = __float2bfloat16(v2);
            l2[j] = __float2bfloat16(v2 - __bfloat162float(h2[j]));
        }
        reinterpret_cast<uint2*>(g_B1h)[i4] = *(uint2*)h1;
        reinterpret_cast<uint2*>(g_B1l)[i4] = *(uint2*)l1;
        reinterpret_cast<uint2*>(g_B2h)[i4] = *(uint2*)h2;
        reinterpret_cast<uint2*>(g_B2l)[i4] = *(uint2*)l2;
    }
}

// ---------------- cumsum ----------------
__global__ void cumsum_k(const int* __restrict__ t, int* __restrict__ cs) {
    __shared__ int s[LL];
    int b = blockIdx.x, tid = threadIdx.x;
    s[tid] = t[(b << 9) + tid];
    __syncthreads();
    for (int off = 1; off < LL; off <<= 1) {
        int v = (tid >= off) ? s[tid - off] : 0;
        __syncthreads();
        s[tid] += v;
        __syncthreads();
    }
    cs[(b << 9) + tid] = s[tid];
}

// ---------------- length regulate (exact) ----------------
__global__ void regulate(const float* __restrict__ x,
                         const int* __restrict__ cs,
                         float* __restrict__ out) {
    int warp = threadIdx.x >> 5, lane = threadIdx.x & 31;
    int gm = blockIdx.x * 8 + warp;
    int b = gm >> 11;
    int m = gm & (MM - 1);
    const int* c = cs + (b << 9);
    int total = c[LL - 1];
    float4* dst = reinterpret_cast<float4*>(out) + (size_t)gm * 64;
    if (m < total) {
        int lo = 0, hi = LL - 1;
        while (lo < hi) {
            int mid = (lo + hi) >> 1;
            if (c[mid] > m) hi = mid; else lo = mid + 1;
        }
        const float4* src =
            reinterpret_cast<const float4*>(x) + ((size_t)((b << 9) + lo)) * 64;
        dst[lane] = src[lane];
        dst[lane + 32] = src[lane + 32];
    } else {
        float4 z = make_float4(0.f, 0.f, 0.f, 0.f);
        dst[lane] = z;
        dst[lane + 32] = z;
    }
}

// ---------------- mma.sync conv(K=3) + bias + LN + ReLU (+linear) ----------
// CTA: 64 rows x 256 channels; 16 warps (2m x 8n), warp tile 32x32.
// A smem: 66 rows x 32 bf16 (+pad) = 66*80B; B smem: 256 x (3*32+8) bf16 = 256*208B.
#define S_PAR  0                 // bias/g/be/lw: 4 x 1KB
#define S_BUF0 4096
#define ASZ    (66 * 80)         // 5280
#define BSZ    (256 * 208)       // 53248
#define BUFSZ  (ASZ + BSZ)       // 58528
#define S_TOTAL (4096 + 2 * BUFSZ)  // 121152

__global__ void __launch_bounds__(512, 1)
conv_mma(const __nv_bfloat16* __restrict__ a_hi,
         const __nv_bfloat16* __restrict__ a_lo,
         const __nv_bfloat16* __restrict__ b_hi,
         const __nv_bfloat16* __restrict__ b_lo,
         const float* __restrict__ bias,
         const float* __restrict__ gamma,
         const float* __restrict__ beta,
         int mode,
         __nv_bfloat16* __restrict__ out_hi,
         __nv_bfloat16* __restrict__ out_lo,
         const float* __restrict__ lw,
         const float* __restrict__ lb,
         float* __restrict__ dup) {
    extern __shared__ char sm[];
    const uint32_t sb = smem_u32(sm);
    const int tid = threadIdx.x;
    const int lane = tid & 31;
    const int wid = tid >> 5;
    const int wm = wid & 1;          // m half: rows wm*32..+31
    const int wn = wid >> 1;         // n eighth: cols wn*32..+31
    const int row0 = blockIdx.x * 64;
    const int l0 = row0 & 511;

    float* s_bias = (float*)(sm + S_PAR);
    float* s_g = (float*)(sm + S_PAR + 1024);
    float* s_be = (float*)(sm + S_PAR + 2048);
    float* s_lw = (float*)(sm + S_PAR + 3072);
    if (tid < 256) {
        s_bias[tid] = bias[tid];
        s_g[tid] = gamma[tid];
        s_be[tid] = beta[tid];
        s_lw[tid] = (mode == 1) ? lw[tid] : 0.f;
    }

    // per-lane ldmatrix base offsets (bytes)
    const uint32_t aL = (uint32_t)((wm * 32 + (lane & 15)) * 80 + (lane >> 4) * 16);
    const uint32_t bL = (uint32_t)((wn * 32 + (lane & 7) + ((lane >> 4) << 3)) * 208 +
                                   ((lane >> 3) & 1) * 16);

    float d[2][4][4];
#pragma unroll
    for (int tm = 0; tm < 2; tm++)
#pragma unroll
        for (int tn = 0; tn < 4; tn++)
#pragma unroll
            for (int j = 0; j < 4; j++) d[tm][tn][j] = 0.f;

    // -------- staging (cp.async) --------
    auto stage = [&](int it) {
        int p = it >> 3, kc = it & 7, buf = it & 1;
        const __nv_bfloat16* ap = (p < 2) ? a_hi : a_lo;   // hh, hl, lh
        const __nv_bfloat16* bp = (p == 1) ? b_lo : b_hi;
        uint32_t sa = sb + S_BUF0 + buf * BUFSZ;
        uint32_t sB = sa + ASZ;
        // A: 66 rows x 64B = 264 cp16 ops (first 264 threads)
        if (tid < 264) {
            int r = tid >> 2, c = tid & 3;
            int l = l0 - 1 + r;
            int v = ((unsigned)l < 512u) ? 1 : 0;
            long grow = (long)row0 - 1 + r;
            const __nv_bfloat16* src = ap + (v ? (grow * 256 + kc * 32 + c * 8) : 0);
            cp16(sa + (uint32_t)(r * 80 + c * 16), src, v);
        }
        // B: contiguous 48KB block = 3072 cp16 ops (6/thread)
        const __nv_bfloat16* bbase = bp + (size_t)kc * 24576;
#pragma unroll
        for (int i = 0; i < 6; i++) {
            int u = i * 512 + tid;
            int f = u / 12, rem = u % 12;
            int tap = rem >> 2, c = rem & 3;
            cp16(sB + (uint32_t)(f * 208 + tap * 64 + c * 16), bbase + u * 8, 1);
        }
        cp_commit();
    };

    stage(0);

    for (int it = 0; it < 24; it++) {
        if (it + 1 < 24) stage(it + 1);
        if (it + 1 < 24) cp_wait1(); else cp_wait0();
        __syncthreads();

        const uint32_t Ab = sb + S_BUF0 + (uint32_t)(it & 1) * BUFSZ;
        const uint32_t Bb = Ab + ASZ;
#pragma unroll
        for (int tap = 0; tap < 3; tap++) {
#pragma unroll
            for (int ko = 0; ko < 2; ko++) {
                uint32_t a[2][4];
#pragma unroll
                for (int tm = 0; tm < 2; tm++)
                    ldsm4(a[tm], Ab + aL + (uint32_t)(tm * 1280 + tap * 80 + ko * 32));
                uint32_t b[4][2];
#pragma unroll
                for (int g = 0; g < 2; g++) {
                    uint32_t r[4];
                    ldsm4(r, Bb + bL + (uint32_t)(g * 3328 + tap * 64 + ko * 32));
                    b[2 * g][0] = r[0];
                    b[2 * g][1] = r[1];
                    b[2 * g + 1][0] = r[2];
                    b[2 * g + 1][1] = r[3];
                }
#pragma unroll
                for (int tm = 0; tm < 2; tm++)
#pragma unroll
                    for (int tn = 0; tn < 4; tn++)
                        mma16816(d[tm][tn], a[tm], b[tn]);
            }
        }
        __syncthreads();
    }

    // -------- epilogue: accums -> smem stats, LN per row --------
    float* stats = (float*)(sm + S_BUF0);       // 64 x 264 fp32 (reuses buffers)
#pragma unroll
    for (int tm = 0; tm < 2; tm++) {
#pragma unroll
        for (int tn = 0; tn < 4; tn++) {
            int m = wm * 32 + tm * 16 + (lane >> 2);
            int n = wn * 32 + tn * 8 + (lane & 3) * 2;
            stats[m * 264 + n] = d[tm][tn][0] + s_bias[n];
            stats[m * 264 + n + 1] = d[tm][tn][1] + s_bias[n + 1];
            stats[(m + 8) * 264 + n] = d[tm][tn][2] + s_bias[n];
            stats[(m + 8) * 264 + n + 1] = d[tm][tn][3] + s_bias[n + 1];
        }
    }
    __syncthreads();

    // 8 threads per row: tid>>3 = row (0..63), tid&7 = 32-channel octant
    const int row = tid >> 3, q = tid & 7;
    const float* rp = stats + row * 264 + q * 32;
    float sum = 0.f, ssq = 0.f;
#pragma unroll
    for (int i = 0; i < 32; i++) {
        float v = rp[i];
        sum += v;
        ssq = fmaf(v, v, ssq);
    }
#pragma unroll
    for (int o = 1; o < 8; o <<= 1) {
        sum += __shfl_xor_sync(0xffffffffu, sum, o);
        ssq += __shfl_xor_sync(0xffffffffu, ssq, o);
    }
    float mu = sum * (1.f / 256.f);
    float rs = rsqrtf(ssq * (1.f / 256.f) - mu * mu + EPSV);

    if (mode == 1) {
        float dot = 0.f;
#pragma unroll
        for (int i = 0; i < 32; i++) {
            int c = q * 32 + i;
            float y = fmaxf((rp[i] - mu) * rs * s_g[c] + s_be[c], 0.f);
            dot = fmaf(y, s_lw[c], dot);
        }
#pragma unroll
        for (int o = 1; o < 8; o <<= 1)
            dot += __shfl_xor_sync(0xffffffffu, dot, o);
        if (q == 0) dup[row0 + row] = fmaxf(dot + lb[0], 0.f);
    } else {
        // 4 x (8 bf16) vector stores per thread for hi and lo
#pragma unroll
        for (int v8 = 0; v8 < 4; v8++) {
            __nv_bfloat16 h[8], l[8];
#pragma unroll
            for (int j = 0; j < 8; j++) {
                int c = q * 32 + v8 * 8 + j;
                float y = fmaxf((rp[v8 * 8 + j] - mu) * rs * s_g[c] + s_be[c], 0.f);
                h[j] = __float2bfloat16(y);
                l[j] = __float2bfloat16(y - __bfloat162float(h[j]));
            }
            size_t go = (size_t)(row0 + row) * 256 + q * 32 + v8 * 8;
            *(uint4*)(out_hi + go) = *(uint4*)h;
            *(uint4*)(out_lo + go) = *(uint4*)l;
        }
    }
}

// ---------------------------------------------------------------------------
extern "C" void kernel_launch(void* const* d_in, const int* in_sizes, int n_in,
                              void* d_out, int out_size) {
    const float* x      = (const float*)d_in[0];
    const int*   target = (const int*)d_in[1];
    const float* w1  = (const float*)d_in[3];
    const float* b1  = (const float*)d_in[4];
    const float* g1  = (const float*)d_in[5];
    const float* be1 = (const float*)d_in[6];
    const float* w2  = (const float*)d_in[7];
    const float* b2  = (const float*)d_in[8];
    const float* g2  = (const float*)d_in[9];
    const float* be2 = (const float*)d_in[10];
    const float* lw  = (const float*)d_in[11];
    const float* lb  = (const float*)d_in[12];

    float* out = (float*)d_out;
    float* dup = out + (size_t)BB * MM * DD;

    __nv_bfloat16 *xhi, *xlo, *h1hi, *h1lo, *B1h, *B1l, *B2h, *B2l;
    int* cs;
    cudaGetSymbolAddress((void**)&xhi, g_xhi);
    cudaGetSymbolAddress((void**)&xlo, g_xlo);
    cudaGetSymbolAddress((void**)&h1hi, g_h1hi);
    cudaGetSymbolAddress((void**)&h1lo, g_h1lo);
    cudaGetSymbolAddress((void**)&B1h, g_B1h);
    cudaGetSymbolAddress((void**)&B1l, g_B1l);
    cudaGetSymbolAddress((void**)&B2h, g_B2h);
    cudaGetSymbolAddress((void**)&B2l, g_B2l);
    cudaGetSymbolAddress((void**)&cs, g_cs);

    cudaFuncSetAttribute((const void*)conv_mma,
                         cudaFuncAttributeMaxDynamicSharedMemorySize, S_TOTAL);

    prep_convert<<<(BB * LL * DD / 4 + 255) / 256, 256>>>(x, w1, w2);
    cumsum_k<<<BB, LL>>>(target, cs);
    regulate<<<BB * MM / 8, 256>>>(x, cs, out);

    conv_mma<<<BB * LL / 64, 512, S_TOTAL>>>(xhi, xlo, B1h, B1l, b1, g1, be1, 0,
                                             h1hi, h1lo, lw, lb, dup);
    conv_mma<<<BB * LL / 64, 512, S_TOTAL>>>(h1hi, h1lo, B2h, B2l, b2, g2, be2, 1,
                                             h1hi, h1lo, lw, lb, dup);
}

// round 6
// speedup vs baseline: 1.1360x; 1.1360x over previous
#include <cuda_runtime.h>
#include <cuda_bf16.h>
#include <cstdint>

#define BB 16
#define LL 512
#define DD 256
#define FF 256
#define MM 2048
#define EPSV 1e-5f

// ---------------- device scratch (16B aligned for cp.async/ldmatrix) --------
__device__ __align__(16) __nv_bfloat16 g_xhi[BB * LL * DD];
__device__ __align__(16) __nv_bfloat16 g_xlo[BB * LL * DD];
__device__ __align__(16) __nv_bfloat16 g_h1hi[BB * LL * FF];
__device__ __align__(16) __nv_bfloat16 g_h1lo[BB * LL * FF];
// weights staged as [kc=8][f=256][tap=3][d=32]  (196608 elems each)
__device__ __align__(16) __nv_bfloat16 g_B1h[8 * 256 * 3 * 32];
__device__ __align__(16) __nv_bfloat16 g_B1l[8 * 256 * 3 * 32];
__device__ __align__(16) __nv_bfloat16 g_B2h[8 * 256 * 3 * 32];
__device__ __align__(16) __nv_bfloat16 g_B2l[8 * 256 * 3 * 32];
__device__ int g_cs[BB * LL];

// ---------------- helpers ----------------
__device__ __forceinline__ uint32_t smem_u32(const void* p) {
    uint32_t a;
    asm("{ .reg .u64 t; cvta.to.shared.u64 t, %1; cvt.u32.u64 %0, t; }"
        : "=r"(a) : "l"(p));
    return a;
}

__device__ __forceinline__ void cp16(uint32_t dst, const void* src, int valid) {
    int sz = valid ? 16 : 0;
    asm volatile("cp.async.cg.shared.global [%0], [%1], %2, %3;"
                 :: "r"(dst), "l"(src), "n"(16), "r"(sz));
}
__device__ __forceinline__ void cp_commit() {
    asm volatile("cp.async.commit_group;" ::: "memory");
}
__device__ __forceinline__ void cp_wait1() {
    asm volatile("cp.async.wait_group 1;" ::: "memory");
}
__device__ __forceinline__ void cp_wait0() {
    asm volatile("cp.async.wait_group 0;" ::: "memory");
}

__device__ __forceinline__ void ldsm4(uint32_t* r, uint32_t addr) {
    asm volatile("ldmatrix.sync.aligned.m8n8.x4.shared.b16 {%0,%1,%2,%3}, [%4];"
                 : "=r"(r[0]), "=r"(r[1]), "=r"(r[2]), "=r"(r[3]) : "r"(addr));
}

__device__ __forceinline__ void mma16816(float* d, const uint32_t* a,
                                         const uint32_t* b) {
    asm volatile(
        "mma.sync.aligned.m16n8k16.row.col.f32.bf16.bf16.f32 "
        "{%0,%1,%2,%3}, {%4,%5,%6,%7}, {%8,%9}, {%0,%1,%2,%3};"
        : "+f"(d[0]), "+f"(d[1]), "+f"(d[2]), "+f"(d[3])
        : "r"(a[0]), "r"(a[1]), "r"(a[2]), "r"(a[3]), "r"(b[0]), "r"(b[1]));
}

// ---------------- prep: bf16 hi/lo splits (vectorized) ----------------
__global__ void prep_convert(const float* __restrict__ x,
                             const float* __restrict__ w1,
                             const float* __restrict__ w2) {
    int i4 = blockIdx.x * 256 + threadIdx.x;   // vec4 index
    if (i4 < BB * LL * DD / 4) {
        float4 v = reinterpret_cast<const float4*>(x)[i4];
        __nv_bfloat16 h[4], l[4];
        float vv[4] = {v.x, v.y, v.z, v.w};
#pragma unroll
        for (int j = 0; j < 4; j++) {
            h[j] = __float2bfloat16(vv[j]);
            l[j] = __float2bfloat16(vv[j] - __bfloat162float(h[j]));
        }
        reinterpret_cast<uint2*>(g_xhi)[i4] = *(uint2*)h;
        reinterpret_cast<uint2*>(g_xlo)[i4] = *(uint2*)l;
    }
    if (i4 < 8 * 256 * 3 * 32 / 4) {
        __nv_bfloat16 h1[4], l1[4], h2[4], l2[4];
#pragma unroll
        for (int j = 0; j < 4; j++) {
            int i = i4 * 4 + j;
            // dst layout [kc][f][tap][32d];  src w[f][d][tap], d = kc*32+d0
            int kc = i / 24576, r = i % 24576;
            int f = r / 96, r2 = r % 96;
            int tap = r2 / 32, d0 = r2 % 32;
            int d = kc * 32 + d0;
            float v1 = w1[f * 768 + d * 3 + tap];
            h1[j] = __float2bfloat16(v1);
            l1[j] = __float2bfloat16(v1 - __bfloat162float(h1[j]));
            float v2 = w2[f * 768 + d * 3 + tap];
            h2[j] = __float2bfloat16(v2);
            l2[j] = __float2bfloat16(v2 - __bfloat162float(h2[j]));
        }
        reinterpret_cast<uint2*>(g_B1h)[i4] = *(uint2*)h1;
        reinterpret_cast<uint2*>(g_B1l)[i4] = *(uint2*)l1;
        reinterpret_cast<uint2*>(g_B2h)[i4] = *(uint2*)h2;
        reinterpret_cast<uint2*>(g_B2l)[i4] = *(uint2*)l2;
    }
}

// ---------------- cumsum ----------------
__global__ void cumsum_k(const int* __restrict__ t, int* __restrict__ cs) {
    __shared__ int s[LL];
    int b = blockIdx.x, tid = threadIdx.x;
    s[tid] = t[(b << 9) + tid];
    __syncthreads();
    for (int off = 1; off < LL; off <<= 1) {
        int v = (tid >= off) ? s[tid - off] : 0;
        __syncthreads();
        s[tid] += v;
        __syncthreads();
    }
    cs[(b << 9) + tid] = s[tid];
}

// ---------------- length regulate (exact) ----------------
__global__ void regulate(const float* __restrict__ x,
                         const int* __restrict__ cs,
                         float* __restrict__ out) {
    int warp = threadIdx.x >> 5, lane = threadIdx.x & 31;
    int gm = blockIdx.x * 8 + warp;
    int b = gm >> 11;
    int m = gm & (MM - 1);
    const int* c = cs + (b << 9);
    int total = c[LL - 1];
    float4* dst = reinterpret_cast<float4*>(out) + (size_t)gm * 64;
    if (m < total) {
        int lo = 0, hi = LL - 1;
        while (lo < hi) {
            int mid = (lo + hi) >> 1;
            if (c[mid] > m) hi = mid; else lo = mid + 1;
        }
        const float4* src =
            reinterpret_cast<const float4*>(x) + ((size_t)((b << 9) + lo)) * 64;
        dst[lane] = src[lane];
        dst[lane + 32] = src[lane + 32];
    } else {
        float4 z = make_float4(0.f, 0.f, 0.f, 0.f);
        dst[lane] = z;
        dst[lane + 32] = z;
    }
}

// ---------------- mma.sync conv(K=3) + bias + LN + ReLU (+linear) ----------
// CTA: 64 rows x 256 channels; 8 warps (2m x 4n), warp tile 32x64.
// A smem: 66 rows x 32 bf16 (+pad) = 66*80B; B smem: 256 x (3*32+8) bf16 = 256*208B.
// Triple-buffered stages; ONE barrier per stage; register-level frag prefetch.
#define S_PAR  0                 // bias/g/be/lw: 4 x 1KB
#define S_BUF0 4096
#define ASZ    (66 * 80)         // 5280
#define BSZ    (256 * 208)       // 53248
#define BUFSZ  (ASZ + BSZ)       // 58528
#define S_TOTAL (4096 + 3 * BUFSZ)  // 179680

__global__ void __launch_bounds__(256, 1)
conv_mma(const __nv_bfloat16* __restrict__ a_hi,
         const __nv_bfloat16* __restrict__ a_lo,
         const __nv_bfloat16* __restrict__ b_hi,
         const __nv_bfloat16* __restrict__ b_lo,
         const float* __restrict__ bias,
         const float* __restrict__ gamma,
         const float* __restrict__ beta,
         int mode,
         __nv_bfloat16* __restrict__ out_hi,
         __nv_bfloat16* __restrict__ out_lo,
         const float* __restrict__ lw,
         const float* __restrict__ lb,
         float* __restrict__ dup) {
    extern __shared__ char sm[];
    const uint32_t sb = smem_u32(sm);
    const int tid = threadIdx.x;
    const int lane = tid & 31;
    const int wid = tid >> 5;
    const int wm = wid & 1;          // m half: rows wm*32..+31
    const int wn = wid >> 1;         // n quarter: cols wn*64..+63
    const int row0 = blockIdx.x * 64;
    const int l0 = row0 & 511;

    float* s_bias = (float*)(sm + S_PAR);
    float* s_g = (float*)(sm + S_PAR + 1024);
    float* s_be = (float*)(sm + S_PAR + 2048);
    float* s_lw = (float*)(sm + S_PAR + 3072);
    s_bias[tid] = bias[tid];
    s_g[tid] = gamma[tid];
    s_be[tid] = beta[tid];
    s_lw[tid] = (mode == 1) ? lw[tid] : 0.f;

    // per-lane ldmatrix base offsets (bytes)
    const uint32_t aL = (uint32_t)((wm * 32 + (lane & 15)) * 80 + (lane >> 4) * 16);
    const uint32_t bL = (uint32_t)((wn * 64 + (lane & 7) + ((lane >> 4) << 3)) * 208 +
                                   ((lane >> 3) & 1) * 16);

    float d[2][8][4];
#pragma unroll
    for (int tm = 0; tm < 2; tm++)
#pragma unroll
        for (int tn = 0; tn < 8; tn++)
#pragma unroll
            for (int j = 0; j < 4; j++) d[tm][tn][j] = 0.f;

    // -------- staging (cp.async), buf = it % 3 --------
    auto stage = [&](int it) {
        int p = it >> 3, kc = it & 7, buf = it % 3;
        const __nv_bfloat16* ap = (p < 2) ? a_hi : a_lo;   // hh, hl, lh
        const __nv_bfloat16* bp = (p == 1) ? b_lo : b_hi;
        uint32_t sa = sb + S_BUF0 + (uint32_t)buf * BUFSZ;
        uint32_t sB = sa + ASZ;
        // A: 66 rows x 64B = 264 cp16 ops
        for (int idx = tid; idx < 264; idx += 256) {
            int r = idx >> 2, c = idx & 3;
            int l = l0 - 1 + r;
            int v = ((unsigned)l < 512u) ? 1 : 0;
            long grow = (long)row0 - 1 + r;
            const __nv_bfloat16* src = ap + (v ? (grow * 256 + kc * 32 + c * 8) : 0);
            cp16(sa + (uint32_t)(r * 80 + c * 16), src, v);
        }
        // B: contiguous 48KB block = 3072 cp16 ops (12/thread, coalesced)
        const __nv_bfloat16* bbase = bp + (size_t)kc * 24576;
#pragma unroll
        for (int i = 0; i < 12; i++) {
            int u = i * 256 + tid;
            int f = u / 12, rem = u % 12;
            int tap = rem >> 2, c = rem & 3;
            cp16(sB + (uint32_t)(f * 208 + tap * 64 + c * 16), bbase + u * 8, 1);
        }
        cp_commit();
    };

    stage(0);
    stage(1);

    uint32_t aF[2][2][4];    // [slot][tm][4]
    uint32_t bF[2][8][2];    // [slot][tn][2]

    for (int it = 0; it < 24; it++) {
        if (it < 23) cp_wait1(); else cp_wait0();
        __syncthreads();
        if (it + 2 < 24) stage(it + 2);

        const uint32_t Ab = sb + S_BUF0 + (uint32_t)(it % 3) * BUFSZ;
        const uint32_t Bb = Ab + ASZ;

        // prefetch step 0 into slot 0
        {
#pragma unroll
            for (int tm = 0; tm < 2; tm++)
                ldsm4(aF[0][tm], Ab + aL + (uint32_t)(tm * 1280));
#pragma unroll
            for (int g = 0; g < 4; g++) {
                uint32_t r[4];
                ldsm4(r, Bb + bL + (uint32_t)(g * 3328));
                bF[0][2 * g][0] = r[0];
                bF[0][2 * g][1] = r[1];
                bF[0][2 * g + 1][0] = r[2];
                bF[0][2 * g + 1][1] = r[3];
            }
        }

        // 6 steps: s = tap*2 + ko; prefetch s+1 while mma on s
#pragma unroll
        for (int s = 0; s < 6; s++) {
            const int cs_ = s & 1;
            const int ns_ = (s + 1) & 1;
            if (s < 5) {
                const int tap = (s + 1) >> 1, ko = (s + 1) & 1;
#pragma unroll
                for (int tm = 0; tm < 2; tm++)
                    ldsm4(aF[ns_][tm],
                          Ab + aL + (uint32_t)(tm * 1280 + tap * 80 + ko * 32));
#pragma unroll
                for (int g = 0; g < 4; g++) {
                    uint32_t r[4];
                    ldsm4(r, Bb + bL + (uint32_t)(g * 3328 + tap * 64 + ko * 32));
                    bF[ns_][2 * g][0] = r[0];
                    bF[ns_][2 * g][1] = r[1];
                    bF[ns_][2 * g + 1][0] = r[2];
                    bF[ns_][2 * g + 1][1] = r[3];
                }
            }
#pragma unroll
            for (int tm = 0; tm < 2; tm++)
#pragma unroll
                for (int tn = 0; tn < 8; tn++)
                    mma16816(d[tm][tn], aF[cs_][tm], bF[cs_][tn]);
        }
    }

    __syncthreads();   // all warps done reading buffers before stats reuse

    // -------- epilogue: accums -> smem stats, LN per row --------
    float* stats = (float*)(sm + S_BUF0);       // 64 x 264 fp32 (reuses buffers)
#pragma unroll
    for (int tm = 0; tm < 2; tm++) {
#pragma unroll
        for (int tn = 0; tn < 8; tn++) {
            int m = wm * 32 + tm * 16 + (lane >> 2);
            int n = wn * 64 + tn * 8 + (lane & 3) * 2;
            stats[m * 264 + n] = d[tm][tn][0] + s_bias[n];
            stats[m * 264 + n + 1] = d[tm][tn][1] + s_bias[n + 1];
            stats[(m + 8) * 264 + n] = d[tm][tn][2] + s_bias[n];
            stats[(m + 8) * 264 + n + 1] = d[tm][tn][3] + s_bias[n + 1];
        }
    }
    __syncthreads();

    const int row = tid >> 2, q = tid & 3;
    const float* rp = stats + row * 264 + q * 64;
    float sum = 0.f, ssq = 0.f;
#pragma unroll 8
    for (int i = 0; i < 64; i++) {
        float v = rp[i];
        sum += v;
        ssq = fmaf(v, v, ssq);
    }
    sum += __shfl_xor_sync(0xffffffffu, sum, 1);
    ssq += __shfl_xor_sync(0xffffffffu, ssq, 1);
    sum += __shfl_xor_sync(0xffffffffu, sum, 2);
    ssq += __shfl_xor_sync(0xffffffffu, ssq, 2);
    float mu = sum * (1.f / 256.f);
    float rs = rsqrtf(ssq * (1.f / 256.f) - mu * mu + EPSV);

    if (mode == 1) {
        float dot = 0.f;
#pragma unroll 8
        for (int i = 0; i < 64; i++) {
            int c = q * 64 + i;
            float y = fmaxf((rp[i] - mu) * rs * s_g[c] + s_be[c], 0.f);
            dot = fmaf(y, s_lw[c], dot);
        }
        dot += __shfl_xor_sync(0xffffffffu, dot, 1);
        dot += __shfl_xor_sync(0xffffffffu, dot, 2);
        if (q == 0) dup[row0 + row] = fmaxf(dot + lb[0], 0.f);
    } else {
        // 8 x (8 bf16) vector stores per thread for hi and lo
#pragma unroll
        for (int v8 = 0; v8 < 8; v8++) {
            __nv_bfloat16 h[8], l[8];
#pragma unroll
            for (int j = 0; j < 8; j++) {
                int c = q * 64 + v8 * 8 + j;
                float y = fmaxf((rp[v8 * 8 + j] - mu) * rs * s_g[c] + s_be[c], 0.f);
                h[j] = __float2bfloat16(y);
                l[j] = __float2bfloat16(y - __bfloat162float(h[j]));
            }
            size_t go = (size_t)(row0 + row) * 256 + q * 64 + v8 * 8;
            *(uint4*)(out_hi + go) = *(uint4*)h;
            *(uint4*)(out_lo + go) = *(uint4*)l;
        }
    }
}

// ---------------------------------------------------------------------------
extern "C" void kernel_launch(void* const* d_in, const int* in_sizes, int n_in,
                              void* d_out, int out_size) {
    const float* x      = (const float*)d_in[0];
    const int*   target = (const int*)d_in[1];
    const float* w1  = (const float*)d_in[3];
    const float* b1  = (const float*)d_in[4];
    const float* g1  = (const float*)d_in[5];
    const float* be1 = (const float*)d_in[6];
    const float* w2  = (const float*)d_in[7];
    const float* b2  = (const float*)d_in[8];
    const float* g2  = (const float*)d_in[9];
    const float* be2 = (const float*)d_in[10];
    const float* lw  = (const float*)d_in[11];
    const float* lb  = (const float*)d_in[12];

    float* out = (float*)d_out;
    float* dup = out + (size_t)BB * MM * DD;

    __nv_bfloat16 *xhi, *xlo, *h1hi, *h1lo, *B1h, *B1l, *B2h, *B2l;
    int* cs;
    cudaGetSymbolAddress((void**)&xhi, g_xhi);
    cudaGetSymbolAddress((void**)&xlo, g_xlo);
    cudaGetSymbolAddress((void**)&h1hi, g_h1hi);
    cudaGetSymbolAddress((void**)&h1lo, g_h1lo);
    cudaGetSymbolAddress((void**)&B1h, g_B1h);
    cudaGetSymbolAddress((void**)&B1l, g_B1l);
    cudaGetSymbolAddress((void**)&B2h, g_B2h);
    cudaGetSymbolAddress((void**)&B2l, g_B2l);
    cudaGetSymbolAddress((void**)&cs, g_cs);

    cudaFuncSetAttribute((const void*)conv_mma,
                         cudaFuncAttributeMaxDynamicSharedMemorySize, S_TOTAL);

    prep_convert<<<(BB * LL * DD / 4 + 255) / 256, 256>>>(x, w1, w2);
    cumsum_k<<<BB, LL>>>(target, cs);
    regulate<<<BB * MM / 8, 256>>>(x, cs, out);

    conv_mma<<<BB * LL / 64, 256, S_TOTAL>>>(xhi, xlo, B1h, B1l, b1, g1, be1, 0,
                                             h1hi, h1lo, lw, lb, dup);
    conv_mma<<<BB * LL / 64, 256, S_TOTAL>>>(h1hi, h1lo, B2h, B2l, b2, g2, be2, 1,
                                             h1hi, h1lo, lw, lb, dup);
}

// round 7
// speedup vs baseline: 1.2427x; 1.0940x over previous
#include <cuda_runtime.h>
#include <cuda_bf16.h>
#include <cstdint>

#define BB 16
#define LL 512
#define DD 256
#define FF 256
#define MM 2048
#define EPSV 1e-5f

// ---------------- device scratch (16B aligned for cp.async/ldmatrix) --------
__device__ __align__(16) __nv_bfloat16 g_xhi[BB * LL * DD];
__device__ __align__(16) __nv_bfloat16 g_xlo[BB * LL * DD];
__device__ __align__(16) __nv_bfloat16 g_h1hi[BB * LL * FF];
__device__ __align__(16) __nv_bfloat16 g_h1lo[BB * LL * FF];
// weights staged as [kc=8][f=256][tap=3][d=32]  (196608 elems each)
__device__ __align__(16) __nv_bfloat16 g_B1h[8 * 256 * 3 * 32];
__device__ __align__(16) __nv_bfloat16 g_B1l[8 * 256 * 3 * 32];
__device__ __align__(16) __nv_bfloat16 g_B2h[8 * 256 * 3 * 32];
__device__ __align__(16) __nv_bfloat16 g_B2l[8 * 256 * 3 * 32];
__device__ int g_cs[BB * LL];

// ---------------- helpers ----------------
__device__ __forceinline__ uint32_t smem_u32(const void* p) {
    uint32_t a;
    asm("{ .reg .u64 t; cvta.to.shared.u64 t, %1; cvt.u32.u64 %0, t; }"
        : "=r"(a) : "l"(p));
    return a;
}

__device__ __forceinline__ void cp16(uint32_t dst, const void* src, int valid) {
    int sz = valid ? 16 : 0;
    asm volatile("cp.async.cg.shared.global [%0], [%1], %2, %3;"
                 :: "r"(dst), "l"(src), "n"(16), "r"(sz));
}
__device__ __forceinline__ void cp_commit() {
    asm volatile("cp.async.commit_group;" ::: "memory");
}
__device__ __forceinline__ void cp_wait1() {
    asm volatile("cp.async.wait_group 1;" ::: "memory");
}
__device__ __forceinline__ void cp_wait0() {
    asm volatile("cp.async.wait_group 0;" ::: "memory");
}

__device__ __forceinline__ void ldsm4(uint32_t* r, uint32_t addr) {
    asm volatile("ldmatrix.sync.aligned.m8n8.x4.shared.b16 {%0,%1,%2,%3}, [%4];"
                 : "=r"(r[0]), "=r"(r[1]), "=r"(r[2]), "=r"(r[3]) : "r"(addr));
}

__device__ __forceinline__ void mma16816(float* d, const uint32_t* a,
                                         const uint32_t* b) {
    asm volatile(
        "mma.sync.aligned.m16n8k16.row.col.f32.bf16.bf16.f32 "
        "{%0,%1,%2,%3}, {%4,%5,%6,%7}, {%8,%9}, {%0,%1,%2,%3};"
        : "+f"(d[0]), "+f"(d[1]), "+f"(d[2]), "+f"(d[3])
        : "r"(a[0]), "r"(a[1]), "r"(a[2]), "r"(a[3]), "r"(b[0]), "r"(b[1]));
}

// ---------------- prep: bf16 hi/lo splits (vectorized) ----------------
__global__ void prep_convert(const float* __restrict__ x,
                             const float* __restrict__ w1,
                             const float* __restrict__ w2) {
    int i4 = blockIdx.x * 256 + threadIdx.x;   // vec4 index
    if (i4 < BB * LL * DD / 4) {
        float4 v = reinterpret_cast<const float4*>(x)[i4];
        __nv_bfloat16 h[4], l[4];
        float vv[4] = {v.x, v.y, v.z, v.w};
#pragma unroll
        for (int j = 0; j < 4; j++) {
            h[j] = __float2bfloat16(vv[j]);
            l[j] = __float2bfloat16(vv[j] - __bfloat162float(h[j]));
        }
        reinterpret_cast<uint2*>(g_xhi)[i4] = *(uint2*)h;
        reinterpret_cast<uint2*>(g_xlo)[i4] = *(uint2*)l;
    }
    if (i4 < 8 * 256 * 3 * 32 / 4) {
        __nv_bfloat16 h1[4], l1[4], h2[4], l2[4];
#pragma unroll
        for (int j = 0; j < 4; j++) {
            int i = i4 * 4 + j;
            // dst layout [kc][f][tap][32d];  src w[f][d][tap], d = kc*32+d0
            int kc = i / 24576, r = i % 24576;
            int f = r / 96, r2 = r % 96;
            int tap = r2 / 32, d0 = r2 % 32;
            int d = kc * 32 + d0;
            float v1 = w1[f * 768 + d * 3 + tap];
            h1[j] = __float2bfloat16(v1);
            l1[j] = __float2bfloat16(v1 - __bfloat162float(h1[j]));
            float v2 = w2[f * 768 + d * 3 + tap];
            h2[j] = __float2bfloat16(v2);
            l2[j] = __float2bfloat16(v2 - __bfloat162float(h2[j]));
        }
        reinterpret_cast<uint2*>(g_B1h)[i4] = *(uint2*)h1;
        reinterpret_cast<uint2*>(g_B1l)[i4] = *(uint2*)l1;
        reinterpret_cast<uint2*>(g_B2h)[i4] = *(uint2*)h2;
        reinterpret_cast<uint2*>(g_B2l)[i4] = *(uint2*)l2;
    }
}

// ---------------- cumsum ----------------
__global__ void cumsum_k(const int* __restrict__ t, int* __restrict__ cs) {
    __shared__ int s[LL];
    int b = blockIdx.x, tid = threadIdx.x;
    s[tid] = t[(b << 9) + tid];
    __syncthreads();
    for (int off = 1; off < LL; off <<= 1) {
        int v = (tid >= off) ? s[tid - off] : 0;
        __syncthreads();
        s[tid] += v;
        __syncthreads();
    }
    cs[(b << 9) + tid] = s[tid];
}

// ---------------- length regulate (exact) ----------------
__global__ void regulate(const float* __restrict__ x,
                         const int* __restrict__ cs,
                         float* __restrict__ out) {
    int warp = threadIdx.x >> 5, lane = threadIdx.x & 31;
    int gm = blockIdx.x * 8 + warp;
    int b = gm >> 11;
    int m = gm & (MM - 1);
    const int* c = cs + (b << 9);
    int total = c[LL - 1];
    float4* dst = reinterpret_cast<float4*>(out) + (size_t)gm * 64;
    if (m < total) {
        int lo = 0, hi = LL - 1;
        while (lo < hi) {
            int mid = (lo + hi) >> 1;
            if (c[mid] > m) hi = mid; else lo = mid + 1;
        }
        const float4* src =
            reinterpret_cast<const float4*>(x) + ((size_t)((b << 9) + lo)) * 64;
        dst[lane] = src[lane];
        dst[lane + 32] = src[lane + 32];
    } else {
        float4 z = make_float4(0.f, 0.f, 0.f, 0.f);
        dst[lane] = z;
        dst[lane + 32] = z;
    }
}

// ---------------- mma.sync conv(K=3) + bias + LN + ReLU (+linear) ----------
// CTA: 64 rows x 256 channels; 8 warps (2m x 4n), warp tile 32x64.
// 16 stages (8 kc x {X,Y}). X: {B_hi, A_hi, A_lo} -> hh + lh (32 mma/step).
// Y: {B_lo, A_hi} -> hl (16 mma/step). B frags loaded once per step.
#define S_PAR  0                 // bias/g/be/lw: 4 x 1KB
#define S_BUF0 4096
#define ASZ    (66 * 80)         // 5280
#define BSZ    (256 * 208)       // 53248
#define BUFSZ  (BSZ + 2 * ASZ)   // 63808
#define S_TOTAL (4096 + 3 * BUFSZ)  // 195520

__global__ void __launch_bounds__(256, 1)
conv_mma(const __nv_bfloat16* __restrict__ a_hi,
         const __nv_bfloat16* __restrict__ a_lo,
         const __nv_bfloat16* __restrict__ b_hi,
         const __nv_bfloat16* __restrict__ b_lo,
         const float* __restrict__ bias,
         const float* __restrict__ gamma,
         const float* __restrict__ beta,
         int mode,
         __nv_bfloat16* __restrict__ out_hi,
         __nv_bfloat16* __restrict__ out_lo,
         const float* __restrict__ lw,
         const float* __restrict__ lb,
         float* __restrict__ dup) {
    extern __shared__ char sm[];
    const uint32_t sb = smem_u32(sm);
    const int tid = threadIdx.x;
    const int lane = tid & 31;
    const int wid = tid >> 5;
    const int wm = wid & 1;          // m half: rows wm*32..+31
    const int wn = wid >> 1;         // n quarter: cols wn*64..+63
    const int row0 = blockIdx.x * 64;
    const int l0 = row0 & 511;

    float* s_bias = (float*)(sm + S_PAR);
    float* s_g = (float*)(sm + S_PAR + 1024);
    float* s_be = (float*)(sm + S_PAR + 2048);
    float* s_lw = (float*)(sm + S_PAR + 3072);
    s_bias[tid] = bias[tid];
    s_g[tid] = gamma[tid];
    s_be[tid] = beta[tid];
    s_lw[tid] = (mode == 1) ? lw[tid] : 0.f;

    // per-lane ldmatrix base offsets (bytes)
    const uint32_t aL = (uint32_t)((wm * 32 + (lane & 15)) * 80 + (lane >> 4) * 16);
    const uint32_t bL = (uint32_t)((wn * 64 + (lane & 7) + ((lane >> 4) << 3)) * 208 +
                                   ((lane >> 3) & 1) * 16);

    float d[2][8][4];
#pragma unroll
    for (int tm = 0; tm < 2; tm++)
#pragma unroll
        for (int tn = 0; tn < 8; tn++)
#pragma unroll
            for (int j = 0; j < 4; j++) d[tm][tn][j] = 0.f;

    // -------- staging (cp.async), buf = st % 3 --------
    // buffer layout: [B: 53248][A1(=A_hi): 5280][A2(=A_lo): 5280]
    auto stage = [&](int st) {
        int kc = st >> 1, ty = st & 1, buf = st % 3;
        uint32_t base = sb + S_BUF0 + (uint32_t)buf * BUFSZ;
        uint32_t sB = base, sA1 = base + BSZ, sA2 = base + BSZ + ASZ;
        const __nv_bfloat16* bp = ty ? b_lo : b_hi;
        // B: contiguous 48KB block = 3072 cp16 ops (12/thread, coalesced)
        const __nv_bfloat16* bbase = bp + (size_t)kc * 24576;
#pragma unroll
        for (int i = 0; i < 12; i++) {
            int u = i * 256 + tid;
            int f = u / 12, rem = u % 12;
            int tap = rem >> 2, c = rem & 3;
            cp16(sB + (uint32_t)(f * 208 + tap * 64 + c * 16), bbase + u * 8, 1);
        }
        // A_hi: 66 rows x 64B = 264 cp16 ops
        for (int idx = tid; idx < 264; idx += 256) {
            int r = idx >> 2, c = idx & 3;
            int l = l0 - 1 + r;
            int v = ((unsigned)l < 512u) ? 1 : 0;
            long grow = (long)row0 - 1 + r;
            const __nv_bfloat16* src = a_hi + (v ? (grow * 256 + kc * 32 + c * 8) : 0);
            cp16(sA1 + (uint32_t)(r * 80 + c * 16), src, v);
        }
        // A_lo only for X stages
        if (!ty) {
            for (int idx = tid; idx < 264; idx += 256) {
                int r = idx >> 2, c = idx & 3;
                int l = l0 - 1 + r;
                int v = ((unsigned)l < 512u) ? 1 : 0;
                long grow = (long)row0 - 1 + r;
                const __nv_bfloat16* src =
                    a_lo + (v ? (grow * 256 + kc * 32 + c * 8) : 0);
                cp16(sA2 + (uint32_t)(r * 80 + c * 16), src, v);
            }
        }
        cp_commit();
    };

    stage(0);
    stage(1);

    uint32_t ahF[2][2][4];   // [slot][tm][4]
    uint32_t alF[2][2][4];
    uint32_t bF[2][8][2];    // [slot][tn][2]

    for (int st = 0; st < 16; st++) {
        if (st < 15) cp_wait1(); else cp_wait0();
        __syncthreads();
        if (st + 2 < 16) stage(st + 2);

        const int ty = st & 1;
        const uint32_t base = sb + S_BUF0 + (uint32_t)(st % 3) * BUFSZ;
        const uint32_t Bb = base, A1b = base + BSZ, A2b = base + BSZ + ASZ;

        // prefetch step 0 into slot 0
        {
#pragma unroll
            for (int tm = 0; tm < 2; tm++)
                ldsm4(ahF[0][tm], A1b + aL + (uint32_t)(tm * 1280));
            if (!ty) {
#pragma unroll
                for (int tm = 0; tm < 2; tm++)
                    ldsm4(alF[0][tm], A2b + aL + (uint32_t)(tm * 1280));
            }
#pragma unroll
            for (int g = 0; g < 4; g++) {
                uint32_t r[4];
                ldsm4(r, Bb + bL + (uint32_t)(g * 3328));
                bF[0][2 * g][0] = r[0];
                bF[0][2 * g][1] = r[1];
                bF[0][2 * g + 1][0] = r[2];
                bF[0][2 * g + 1][1] = r[3];
            }
        }

        // 6 steps: s = tap*2 + ko; prefetch s+1 while mma on s
#pragma unroll
        for (int s = 0; s < 6; s++) {
            const int cs_ = s & 1;
            const int ns_ = (s + 1) & 1;
            if (s < 5) {
                const int tap = (s + 1) >> 1, ko = (s + 1) & 1;
                const uint32_t ao = (uint32_t)(tap * 80 + ko * 32);
#pragma unroll
                for (int tm = 0; tm < 2; tm++)
                    ldsm4(ahF[ns_][tm], A1b + aL + (uint32_t)(tm * 1280) + ao);
                if (!ty) {
#pragma unroll
                    for (int tm = 0; tm < 2; tm++)
                        ldsm4(alF[ns_][tm], A2b + aL + (uint32_t)(tm * 1280) + ao);
                }
#pragma unroll
                for (int g = 0; g < 4; g++) {
                    uint32_t r[4];
                    ldsm4(r, Bb + bL + (uint32_t)(g * 3328 + tap * 64 + ko * 32));
                    bF[ns_][2 * g][0] = r[0];
                    bF[ns_][2 * g][1] = r[1];
                    bF[ns_][2 * g + 1][0] = r[2];
                    bF[ns_][2 * g + 1][1] = r[3];
                }
            }
#pragma unroll
            for (int tm = 0; tm < 2; tm++)
#pragma unroll
                for (int tn = 0; tn < 8; tn++)
                    mma16816(d[tm][tn], ahF[cs_][tm], bF[cs_][tn]);
            if (!ty) {
#pragma unroll
                for (int tm = 0; tm < 2; tm++)
#pragma unroll
                    for (int tn = 0; tn < 8; tn++)
                        mma16816(d[tm][tn], alF[cs_][tm], bF[cs_][tn]);
            }
        }
    }

    __syncthreads();   // all warps done reading buffers before stats reuse

    // -------- epilogue: accums -> smem stats, LN per row --------
    float* stats = (float*)(sm + S_BUF0);       // 64 x 264 fp32 (reuses buffers)
#pragma unroll
    for (int tm = 0; tm < 2; tm++) {
#pragma unroll
        for (int tn = 0; tn < 8; tn++) {
            int m = wm * 32 + tm * 16 + (lane >> 2);
            int n = wn * 64 + tn * 8 + (lane & 3) * 2;
            stats[m * 264 + n] = d[tm][tn][0] + s_bias[n];
            stats[m * 264 + n + 1] = d[tm][tn][1] + s_bias[n + 1];
            stats[(m + 8) * 264 + n] = d[tm][tn][2] + s_bias[n];
            stats[(m + 8) * 264 + n + 1] = d[tm][tn][3] + s_bias[n + 1];
        }
    }
    __syncthreads();

    const int row = tid >> 2, q = tid & 3;
    const float* rp = stats + row * 264 + q * 64;
    float sum = 0.f, ssq = 0.f;
#pragma unroll 8
    for (int i = 0; i < 64; i++) {
        float v = rp[i];
        sum += v;
        ssq = fmaf(v, v, ssq);
    }
    sum += __shfl_xor_sync(0xffffffffu, sum, 1);
    ssq += __shfl_xor_sync(0xffffffffu, ssq, 1);
    sum += __shfl_xor_sync(0xffffffffu, sum, 2);
    ssq += __shfl_xor_sync(0xffffffffu, ssq, 2);
    float mu = sum * (1.f / 256.f);
    float rs = rsqrtf(ssq * (1.f / 256.f) - mu * mu + EPSV);

    if (mode == 1) {
        float dot = 0.f;
#pragma unroll 8
        for (int i = 0; i < 64; i++) {
            int c = q * 64 + i;
            float y = fmaxf((rp[i] - mu) * rs * s_g[c] + s_be[c], 0.f);
            dot = fmaf(y, s_lw[c], dot);
        }
        dot += __shfl_xor_sync(0xffffffffu, dot, 1);
        dot += __shfl_xor_sync(0xffffffffu, dot, 2);
        if (q == 0) dup[row0 + row] = fmaxf(dot + lb[0], 0.f);
    } else {
        // 8 x (8 bf16) vector stores per thread for hi and lo
#pragma unroll
        for (int v8 = 0; v8 < 8; v8++) {
            __nv_bfloat16 h[8], l[8];
#pragma unroll
            for (int j = 0; j < 8; j++) {
                int c = q * 64 + v8 * 8 + j;
                float y = fmaxf((rp[v8 * 8 + j] - mu) * rs * s_g[c] + s_be[c], 0.f);
                h[j] = __float2bfloat16(y);
                l[j] = __float2bfloat16(y - __bfloat162float(h[j]));
            }
            size_t go = (size_t)(row0 + row) * 256 + q * 64 + v8 * 8;
            *(uint4*)(out_hi + go) = *(uint4*)h;
            *(uint4*)(out_lo + go) = *(uint4*)l;
        }
    }
}

// ---------------------------------------------------------------------------
extern "C" void kernel_launch(void* const* d_in, const int* in_sizes, int n_in,
                              void* d_out, int out_size) {
    const float* x      = (const float*)d_in[0];
    const int*   target = (const int*)d_in[1];
    const float* w1  = (const float*)d_in[3];
    const float* b1  = (const float*)d_in[4];
    const float* g1  = (const float*)d_in[5];
    const float* be1 = (const float*)d_in[6];
    const float* w2  = (const float*)d_in[7];
    const float* b2  = (const float*)d_in[8];
    const float* g2  = (const float*)d_in[9];
    const float* be2 = (const float*)d_in[10];
    const float* lw  = (const float*)d_in[11];
    const float* lb  = (const float*)d_in[12];

    float* out = (float*)d_out;
    float* dup = out + (size_t)BB * MM * DD;

    __nv_bfloat16 *xhi, *xlo, *h1hi, *h1lo, *B1h, *B1l, *B2h, *B2l;
    int* cs;
    cudaGetSymbolAddress((void**)&xhi, g_xhi);
    cudaGetSymbolAddress((void**)&xlo, g_xlo);
    cudaGetSymbolAddress((void**)&h1hi, g_h1hi);
    cudaGetSymbolAddress((void**)&h1lo, g_h1lo);
    cudaGetSymbolAddress((void**)&B1h, g_B1h);
    cudaGetSymbolAddress((void**)&B1l, g_B1l);
    cudaGetSymbolAddress((void**)&B2h, g_B2h);
    cudaGetSymbolAddress((void**)&B2l, g_B2l);
    cudaGetSymbolAddress((void**)&cs, g_cs);

    cudaFuncSetAttribute((const void*)conv_mma,
                         cudaFuncAttributeMaxDynamicSharedMemorySize, S_TOTAL);

    prep_convert<<<(BB * LL * DD / 4 + 255) / 256, 256>>>(x, w1, w2);
    cumsum_k<<<BB, LL>>>(target, cs);
    regulate<<<BB * MM / 8, 256>>>(x, cs, out);

    conv_mma<<<BB * LL / 64, 256, S_TOTAL>>>(xhi, xlo, B1h, B1l, b1, g1, be1, 0,
                                             h1hi, h1lo, lw, lb, dup);
    conv_mma<<<BB * LL / 64, 256, S_TOTAL>>>(h1hi, h1lo, B2h, B2l, b2, g2, be2, 1,
                                             h1hi, h1lo, lw, lb, dup);
}

// round 8
// speedup vs baseline: 1.5250x; 1.2272x over previous
#include <cuda_runtime.h>
#include <cuda_fp16.h>
#include <cstdint>

#define BB 16
#define LL 512
#define DD 256
#define FF 256
#define MM 2048
#define EPSV 1e-5f

// ---------------- device scratch (16B aligned for cp.async/ldmatrix) --------
__device__ __align__(16) __half g_xh[BB * LL * DD];     // x in fp16
__device__ __align__(16) __half g_h1h[BB * LL * FF];    // conv1 output in fp16
// weights staged as [kc=8][f=256][tap=3][d=32] (196608 elems each), fp16 hi/lo
__device__ __align__(16) __half g_B1h[8 * 256 * 3 * 32];
__device__ __align__(16) __half g_B1l[8 * 256 * 3 * 32];
__device__ __align__(16) __half g_B2h[8 * 256 * 3 * 32];
__device__ __align__(16) __half g_B2l[8 * 256 * 3 * 32];
__device__ int g_cs[BB * LL];

// ---------------- helpers ----------------
__device__ __forceinline__ uint32_t smem_u32(const void* p) {
    uint32_t a;
    asm("{ .reg .u64 t; cvta.to.shared.u64 t, %1; cvt.u32.u64 %0, t; }"
        : "=r"(a) : "l"(p));
    return a;
}

__device__ __forceinline__ void cp16(uint32_t dst, const void* src, int valid) {
    int sz = valid ? 16 : 0;
    asm volatile("cp.async.cg.shared.global [%0], [%1], %2, %3;"
                 :: "r"(dst), "l"(src), "n"(16), "r"(sz));
}
__device__ __forceinline__ void cp_commit() {
    asm volatile("cp.async.commit_group;" ::: "memory");
}
__device__ __forceinline__ void cp_wait1() {
    asm volatile("cp.async.wait_group 1;" ::: "memory");
}
__device__ __forceinline__ void cp_wait0() {
    asm volatile("cp.async.wait_group 0;" ::: "memory");
}

__device__ __forceinline__ void ldsm4(uint32_t* r, uint32_t addr) {
    asm volatile("ldmatrix.sync.aligned.m8n8.x4.shared.b16 {%0,%1,%2,%3}, [%4];"
                 : "=r"(r[0]), "=r"(r[1]), "=r"(r[2]), "=r"(r[3]) : "r"(addr));
}

__device__ __forceinline__ void mma16816(float* d, const uint32_t* a,
                                         const uint32_t* b) {
    asm volatile(
        "mma.sync.aligned.m16n8k16.row.col.f32.f16.f16.f32 "
        "{%0,%1,%2,%3}, {%4,%5,%6,%7}, {%8,%9}, {%0,%1,%2,%3};"
        : "+f"(d[0]), "+f"(d[1]), "+f"(d[2]), "+f"(d[3])
        : "r"(a[0]), "r"(a[1]), "r"(a[2]), "r"(a[3]), "r"(b[0]), "r"(b[1]));
}

// ---------------- prep: x -> fp16; weights -> fp16 hi/lo splits -------------
__global__ void prep_convert(const float* __restrict__ x,
                             const float* __restrict__ w1,
                             const float* __restrict__ w2) {
    int i4 = blockIdx.x * 256 + threadIdx.x;   // vec4 index
    if (i4 < BB * LL * DD / 4) {
        float4 v = reinterpret_cast<const float4*>(x)[i4];
        __half h[4];
        h[0] = __float2half(v.x);
        h[1] = __float2half(v.y);
        h[2] = __float2half(v.z);
        h[3] = __float2half(v.w);
        reinterpret_cast<uint2*>(g_xh)[i4] = *(uint2*)h;
    }
    if (i4 < 8 * 256 * 3 * 32 / 4) {
        __half h1[4], l1[4], h2[4], l2[4];
#pragma unroll
        for (int j = 0; j < 4; j++) {
            int i = i4 * 4 + j;
            // dst layout [kc][f][tap][32d];  src w[f][d][tap], d = kc*32+d0
            int kc = i / 24576, r = i % 24576;
            int f = r / 96, r2 = r % 96;
            int tap = r2 / 32, d0 = r2 % 32;
            int d = kc * 32 + d0;
            float v1 = w1[f * 768 + d * 3 + tap];
            h1[j] = __float2half(v1);
            l1[j] = __float2half(v1 - __half2float(h1[j]));
            float v2 = w2[f * 768 + d * 3 + tap];
            h2[j] = __float2half(v2);
            l2[j] = __float2half(v2 - __half2float(h2[j]));
        }
        reinterpret_cast<uint2*>(g_B1h)[i4] = *(uint2*)h1;
        reinterpret_cast<uint2*>(g_B1l)[i4] = *(uint2*)l1;
        reinterpret_cast<uint2*>(g_B2h)[i4] = *(uint2*)h2;
        reinterpret_cast<uint2*>(g_B2l)[i4] = *(uint2*)l2;
    }
}

// ---------------- cumsum ----------------
__global__ void cumsum_k(const int* __restrict__ t, int* __restrict__ cs) {
    __shared__ int s[LL];
    int b = blockIdx.x, tid = threadIdx.x;
    s[tid] = t[(b << 9) + tid];
    __syncthreads();
    for (int off = 1; off < LL; off <<= 1) {
        int v = (tid >= off) ? s[tid - off] : 0;
        __syncthreads();
        s[tid] += v;
        __syncthreads();
    }
    cs[(b << 9) + tid] = s[tid];
}

// ---------------- length regulate (exact) ----------------
__global__ void regulate(const float* __restrict__ x,
                         const int* __restrict__ cs,
                         float* __restrict__ out) {
    int warp = threadIdx.x >> 5, lane = threadIdx.x & 31;
    int gm = blockIdx.x * 8 + warp;
    int b = gm >> 11;
    int m = gm & (MM - 1);
    const int* c = cs + (b << 9);
    int total = c[LL - 1];
    float4* dst = reinterpret_cast<float4*>(out) + (size_t)gm * 64;
    if (m < total) {
        int lo = 0, hi = LL - 1;
        while (lo < hi) {
            int mid = (lo + hi) >> 1;
            if (c[mid] > m) hi = mid; else lo = mid + 1;
        }
        const float4* src =
            reinterpret_cast<const float4*>(x) + ((size_t)((b << 9) + lo)) * 64;
        dst[lane] = src[lane];
        dst[lane + 32] = src[lane + 32];
    } else {
        float4 z = make_float4(0.f, 0.f, 0.f, 0.f);
        dst[lane] = z;
        dst[lane + 32] = z;
    }
}

// ---------------- fp16 2-pass mma conv(K=3) + bias + LN + ReLU (+linear) ---
// CTA: 64 rows x 256 channels; 8 warps (2m x 4n), warp tile 32x64.
// A (x_hi halo tile, 66x256 fp16, stride 528B) RESIDENT in smem, loaded once.
// B streams: 16 stages (8 kc x {hi,lo}), 53248B each, triple-buffered.
// d += A_hi * B_hi  then  d += A_hi * B_lo  (dropped x_lo*w ~ 2e-4 rel).
#define S_PAR   0                 // bias/g/be/lw: 4 x 1KB
#define S_A     4096
#define A_STR   528               // 256*2 + 16 pad; conflict-free ldsm
#define ASZ_R   (66 * A_STR)      // 34848
#define S_B0    (4096 + ASZ_R)    // 38944
#define BSZ     (256 * 208)       // 53248
#define S_TOTAL (S_B0 + 3 * BSZ)  // 198688

__global__ void __launch_bounds__(256, 1)
conv_mma(const __half* __restrict__ a_in,
         const __half* __restrict__ b_hi,
         const __half* __restrict__ b_lo,
         const float* __restrict__ bias,
         const float* __restrict__ gamma,
         const float* __restrict__ beta,
         int mode,
         __half* __restrict__ out_h,
         const float* __restrict__ lw,
         const float* __restrict__ lb,
         float* __restrict__ dup) {
    extern __shared__ char sm[];
    const uint32_t sb = smem_u32(sm);
    const int tid = threadIdx.x;
    const int lane = tid & 31;
    const int wid = tid >> 5;
    const int wm = wid & 1;          // m half: rows wm*32..+31
    const int wn = wid >> 1;         // n quarter: cols wn*64..+63
    const int row0 = blockIdx.x * 64;
    const int l0 = row0 & 511;

    float* s_bias = (float*)(sm + S_PAR);
    float* s_g = (float*)(sm + S_PAR + 1024);
    float* s_be = (float*)(sm + S_PAR + 2048);
    float* s_lw = (float*)(sm + S_PAR + 3072);
    s_bias[tid] = bias[tid];
    s_g[tid] = gamma[tid];
    s_be[tid] = beta[tid];
    s_lw[tid] = (mode == 1) ? lw[tid] : 0.f;

    // -------- B staging (cp.async), buf = st % 3 --------
    auto stage = [&](int st) {
        int kc = st >> 1, ty = st & 1, buf = st % 3;
        uint32_t sB = sb + S_B0 + (uint32_t)buf * BSZ;
        const __half* bp = ty ? b_lo : b_hi;
        const __half* bbase = bp + (size_t)kc * 24576;
#pragma unroll
        for (int i = 0; i < 12; i++) {
            int u = i * 256 + tid;
            int f = u / 12, rem = u % 12;
            int tap = rem >> 2, c = rem & 3;
            cp16(sB + (uint32_t)(f * 208 + tap * 64 + c * 16), bbase + u * 8, 1);
        }
        cp_commit();
    };

    // -------- load resident A tile (66 rows x 512B), then stage(0) in G0 ----
    {
        for (int idx = tid; idx < 66 * 32; idx += 256) {
            int r = idx >> 5, c = idx & 31;
            int l = l0 - 1 + r;
            int v = ((unsigned)l < 512u) ? 1 : 0;
            long grow = (long)row0 - 1 + r;
            const __half* src = a_in + (v ? (grow * 256 + c * 8) : 0);
            cp16(sb + S_A + (uint32_t)(r * A_STR + c * 16), src, v);
        }
    }
    stage(0);   // commits group G0 = {A, B stage 0}
    stage(1);   // G1

    // per-lane ldmatrix base offsets (bytes)
    const uint32_t aL = sb + S_A +
        (uint32_t)((wm * 32 + (lane & 15)) * A_STR + (lane >> 4) * 16);
    const uint32_t bL = (uint32_t)((wn * 64 + (lane & 7) + ((lane >> 4) << 3)) * 208 +
                                   ((lane >> 3) & 1) * 16);

    float d[2][8][4];
#pragma unroll
    for (int tm = 0; tm < 2; tm++)
#pragma unroll
        for (int tn = 0; tn < 8; tn++)
#pragma unroll
            for (int j = 0; j < 4; j++) d[tm][tn][j] = 0.f;

    uint32_t aF[2][2][4];    // [slot][tm][4]
    uint32_t bF[2][8][2];    // [slot][tn][2]

    for (int st = 0; st < 16; st++) {
        if (st < 15) cp_wait1(); else cp_wait0();
        __syncthreads();
        if (st + 2 < 16) stage(st + 2);

        const int kc = st >> 1;
        const uint32_t Aoff = (uint32_t)(kc * 64);   // col offset bytes
        const uint32_t Bb = sb + S_B0 + (uint32_t)(st % 3) * BSZ;

        // prefetch step 0 (tap=0, ko=0) into slot 0
        {
#pragma unroll
            for (int tm = 0; tm < 2; tm++)
                ldsm4(aF[0][tm], aL + Aoff + (uint32_t)(tm * 16 * A_STR));
#pragma unroll
            for (int g = 0; g < 4; g++) {
                uint32_t r[4];
                ldsm4(r, Bb + bL + (uint32_t)(g * 3328));
                bF[0][2 * g][0] = r[0];
                bF[0][2 * g][1] = r[1];
                bF[0][2 * g + 1][0] = r[2];
                bF[0][2 * g + 1][1] = r[3];
            }
        }

        // 6 steps: s = tap*2 + ko; prefetch s+1 while mma on s
#pragma unroll
        for (int s = 0; s < 6; s++) {
            const int cs_ = s & 1;
            const int ns_ = (s + 1) & 1;
            if (s < 5) {
                const int tap = (s + 1) >> 1, ko = (s + 1) & 1;
#pragma unroll
                for (int tm = 0; tm < 2; tm++)
                    ldsm4(aF[ns_][tm],
                          aL + Aoff +
                          (uint32_t)((tm * 16 + tap) * A_STR + ko * 32));
#pragma unroll
                for (int g = 0; g < 4; g++) {
                    uint32_t r[4];
                    ldsm4(r, Bb + bL + (uint32_t)(g * 3328 + tap * 64 + ko * 32));
                    bF[ns_][2 * g][0] = r[0];
                    bF[ns_][2 * g][1] = r[1];
                    bF[ns_][2 * g + 1][0] = r[2];
                    bF[ns_][2 * g + 1][1] = r[3];
                }
            }
#pragma unroll
            for (int tm = 0; tm < 2; tm++)
#pragma unroll
                for (int tn = 0; tn < 8; tn++)
                    mma16816(d[tm][tn], aF[cs_][tm], bF[cs_][tn]);
        }
    }

    __syncthreads();   // all warps done reading buffers before stats reuse

    // -------- epilogue: accums -> smem stats, LN per row --------
    float* stats = (float*)(sm + S_B0);       // 64 x 264 fp32 (reuses B buffers)
#pragma unroll
    for (int tm = 0; tm < 2; tm++) {
#pragma unroll
        for (int tn = 0; tn < 8; tn++) {
            int m = wm * 32 + tm * 16 + (lane >> 2);
            int n = wn * 64 + tn * 8 + (lane & 3) * 2;
            stats[m * 264 + n] = d[tm][tn][0] + s_bias[n];
            stats[m * 264 + n + 1] = d[tm][tn][1] + s_bias[n + 1];
            stats[(m + 8) * 264 + n] = d[tm][tn][2] + s_bias[n];
            stats[(m + 8) * 264 + n + 1] = d[tm][tn][3] + s_bias[n + 1];
        }
    }
    __syncthreads();

    const int row = tid >> 2, q = tid & 3;
    const float* rp = stats + row * 264 + q * 64;
    float sum = 0.f, ssq = 0.f;
#pragma unroll 8
    for (int i = 0; i < 64; i++) {
        float v = rp[i];
        sum += v;
        ssq = fmaf(v, v, ssq);
    }
    sum += __shfl_xor_sync(0xffffffffu, sum, 1);
    ssq += __shfl_xor_sync(0xffffffffu, ssq, 1);
    sum += __shfl_xor_sync(0xffffffffu, sum, 2);
    ssq += __shfl_xor_sync(0xffffffffu, ssq, 2);
    float mu = sum * (1.f / 256.f);
    float rs = rsqrtf(ssq * (1.f / 256.f) - mu * mu + EPSV);

    if (mode == 1) {
        float dot = 0.f;
#pragma unroll 8
        for (int i = 0; i < 64; i++) {
            int c = q * 64 + i;
            float y = fmaxf((rp[i] - mu) * rs * s_g[c] + s_be[c], 0.f);
            dot = fmaf(y, s_lw[c], dot);
        }
        dot += __shfl_xor_sync(0xffffffffu, dot, 1);
        dot += __shfl_xor_sync(0xffffffffu, dot, 2);
        if (q == 0) dup[row0 + row] = fmaxf(dot + lb[0], 0.f);
    } else {
        // 8 x (8 fp16) vector stores per thread
#pragma unroll
        for (int v8 = 0; v8 < 8; v8++) {
            __half h[8];
#pragma unroll
            for (int j = 0; j < 8; j++) {
                int c = q * 64 + v8 * 8 + j;
                float y = fmaxf((rp[v8 * 8 + j] - mu) * rs * s_g[c] + s_be[c], 0.f);
                h[j] = __float2half(y);
            }
            size_t go = (size_t)(row0 + row) * 256 + q * 64 + v8 * 8;
            *(uint4*)(out_h + go) = *(uint4*)h;
        }
    }
}

// ---------------------------------------------------------------------------
extern "C" void kernel_launch(void* const* d_in, const int* in_sizes, int n_in,
                              void* d_out, int out_size) {
    const float* x      = (const float*)d_in[0];
    const int*   target = (const int*)d_in[1];
    const float* w1  = (const float*)d_in[3];
    const float* b1  = (const float*)d_in[4];
    const float* g1  = (const float*)d_in[5];
    const float* be1 = (const float*)d_in[6];
    const float* w2  = (const float*)d_in[7];
    const float* b2  = (const float*)d_in[8];
    const float* g2  = (const float*)d_in[9];
    const float* be2 = (const float*)d_in[10];
    const float* lw  = (const float*)d_in[11];
    const float* lb  = (const float*)d_in[12];

    float* out = (float*)d_out;
    float* dup = out + (size_t)BB * MM * DD;

    __half *xh, *h1h, *B1h, *B1l, *B2h, *B2l;
    int* cs;
    cudaGetSymbolAddress((void**)&xh, g_xh);
    cudaGetSymbolAddress((void**)&h1h, g_h1h);
    cudaGetSymbolAddress((void**)&B1h, g_B1h);
    cudaGetSymbolAddress((void**)&B1l, g_B1l);
    cudaGetSymbolAddress((void**)&B2h, g_B2h);
    cudaGetSymbolAddress((void**)&B2l, g_B2l);
    cudaGetSymbolAddress((void**)&cs, g_cs);

    cudaFuncSetAttribute((const void*)conv_mma,
                         cudaFuncAttributeMaxDynamicSharedMemorySize, S_TOTAL);

    prep_convert<<<(BB * LL * DD / 4 + 255) / 256, 256>>>(x, w1, w2);
    cumsum_k<<<BB, LL>>>(target, cs);
    regulate<<<BB * MM / 8, 256>>>(x, cs, out);

    conv_mma<<<BB * LL / 64, 256, S_TOTAL>>>(xh, B1h, B1l, b1, g1, be1, 0,
                                             h1h, lw, lb, dup);
    conv_mma<<<BB * LL / 64, 256, S_TOTAL>>>(h1h, B2h, B2l, b2, g2, be2, 1,
                                             h1h, lw, lb, dup);
}

// round 9
// speedup vs baseline: 2.1624x; 1.4180x over previous
#include <cuda_runtime.h>
#include <cuda_fp16.h>
#include <cstdint>

#define BB 16
#define LL 512
#define DD 256
#define FF 256
#define MM 2048
#define EPSV 1e-5f

// ---------------- device scratch (16B aligned for cp.async/ldmatrix) --------
__device__ __align__(16) __half g_xh[BB * LL * DD];     // x in fp16
__device__ __align__(16) __half g_h1h[BB * LL * FF];    // conv1 output in fp16
// weights staged as [kc=8][f=256][tap=3][d=32] (196608 elems each), fp16
__device__ __align__(16) __half g_B1[8 * 256 * 3 * 32];
__device__ __align__(16) __half g_B2[8 * 256 * 3 * 32];
__device__ int g_cs[BB * LL];

// ---------------- helpers ----------------
__device__ __forceinline__ uint32_t smem_u32(const void* p) {
    uint32_t a;
    asm("{ .reg .u64 t; cvta.to.shared.u64 t, %1; cvt.u32.u64 %0, t; }"
        : "=r"(a) : "l"(p));
    return a;
}

__device__ __forceinline__ void cp16(uint32_t dst, const void* src, int valid) {
    int sz = valid ? 16 : 0;
    asm volatile("cp.async.cg.shared.global [%0], [%1], %2, %3;"
                 :: "r"(dst), "l"(src), "n"(16), "r"(sz));
}
__device__ __forceinline__ void cp_commit() {
    asm volatile("cp.async.commit_group;" ::: "memory");
}
__device__ __forceinline__ void cp_wait1() {
    asm volatile("cp.async.wait_group 1;" ::: "memory");
}
__device__ __forceinline__ void cp_wait0() {
    asm volatile("cp.async.wait_group 0;" ::: "memory");
}

__device__ __forceinline__ void ldsm4(uint32_t* r, uint32_t addr) {
    asm volatile("ldmatrix.sync.aligned.m8n8.x4.shared.b16 {%0,%1,%2,%3}, [%4];"
                 : "=r"(r[0]), "=r"(r[1]), "=r"(r[2]), "=r"(r[3]) : "r"(addr));
}

__device__ __forceinline__ void mma16816(float* d, const uint32_t* a,
                                         const uint32_t* b) {
    asm volatile(
        "mma.sync.aligned.m16n8k16.row.col.f32.f16.f16.f32 "
        "{%0,%1,%2,%3}, {%4,%5,%6,%7}, {%8,%9}, {%0,%1,%2,%3};"
        : "+f"(d[0]), "+f"(d[1]), "+f"(d[2]), "+f"(d[3])
        : "r"(a[0]), "r"(a[1]), "r"(a[2]), "r"(a[3]), "r"(b[0]), "r"(b[1]));
}

// ---------------- prep: x, w1, w2 -> fp16 ----------------
__global__ void prep_convert(const float* __restrict__ x,
                             const float* __restrict__ w1,
                             const float* __restrict__ w2) {
    int i4 = blockIdx.x * 256 + threadIdx.x;   // vec4 index
    if (i4 < BB * LL * DD / 4) {
        float4 v = reinterpret_cast<const float4*>(x)[i4];
        __half h[4];
        h[0] = __float2half(v.x);
        h[1] = __float2half(v.y);
        h[2] = __float2half(v.z);
        h[3] = __float2half(v.w);
        reinterpret_cast<uint2*>(g_xh)[i4] = *(uint2*)h;
    }
    if (i4 < 8 * 256 * 3 * 32 / 4) {
        __half h1[4], h2[4];
#pragma unroll
        for (int j = 0; j < 4; j++) {
            int i = i4 * 4 + j;
            // dst layout [kc][f][tap][32d];  src w[f][d][tap], d = kc*32+d0
            int kc = i / 24576, r = i % 24576;
            int f = r / 96, r2 = r % 96;
            int tap = r2 / 32, d0 = r2 % 32;
            int d = kc * 32 + d0;
            h1[j] = __float2half(w1[f * 768 + d * 3 + tap]);
            h2[j] = __float2half(w2[f * 768 + d * 3 + tap]);
        }
        reinterpret_cast<uint2*>(g_B1)[i4] = *(uint2*)h1;
        reinterpret_cast<uint2*>(g_B2)[i4] = *(uint2*)h2;
    }
}

// ---------------- cumsum ----------------
__global__ void cumsum_k(const int* __restrict__ t, int* __restrict__ cs) {
    __shared__ int s[LL];
    int b = blockIdx.x, tid = threadIdx.x;
    s[tid] = t[(b << 9) + tid];
    __syncthreads();
    for (int off = 1; off < LL; off <<= 1) {
        int v = (tid >= off) ? s[tid - off] : 0;
        __syncthreads();
        s[tid] += v;
        __syncthreads();
    }
    cs[(b << 9) + tid] = s[tid];
}

// ---------------- length regulate (exact) ----------------
__global__ void regulate(const float* __restrict__ x,
                         const int* __restrict__ cs,
                         float* __restrict__ out) {
    int warp = threadIdx.x >> 5, lane = threadIdx.x & 31;
    int gm = blockIdx.x * 8 + warp;
    int b = gm >> 11;
    int m = gm & (MM - 1);
    const int* c = cs + (b << 9);
    int total = c[LL - 1];
    float4* dst = reinterpret_cast<float4*>(out) + (size_t)gm * 64;
    if (m < total) {
        int lo = 0, hi = LL - 1;
        while (lo < hi) {
            int mid = (lo + hi) >> 1;
            if (c[mid] > m) hi = mid; else lo = mid + 1;
        }
        const float4* src =
            reinterpret_cast<const float4*>(x) + ((size_t)((b << 9) + lo)) * 64;
        dst[lane] = src[lane];
        dst[lane + 32] = src[lane + 32];
    } else {
        float4 z = make_float4(0.f, 0.f, 0.f, 0.f);
        dst[lane] = z;
        dst[lane + 32] = z;
    }
}

// ---------------- fp16 single-pass conv(K=3) + bias + LN + ReLU (+linear) --
// CTA: 64 rows x 256 channels; 8 warps (2m x 4n), warp tile 32x64.
// A (x halo tile, 66x256 fp16, stride 528B) RESIDENT in smem, loaded once.
// B streams: 8 stages (one per kc), 53248B each, triple-buffered.
#define S_PAR   0                 // bias/g/be/lw: 4 x 1KB
#define S_A     4096
#define A_STR   528               // 256*2 + 16 pad; conflict-free ldsm
#define ASZ_R   (66 * A_STR)      // 34848
#define S_B0    (4096 + ASZ_R)    // 38944
#define BSZ     (256 * 208)       // 53248
#define S_TOTAL (S_B0 + 3 * BSZ)  // 198688

__global__ void __launch_bounds__(256, 1)
conv_mma(const __half* __restrict__ a_in,
         const __half* __restrict__ b_w,
         const float* __restrict__ bias,
         const float* __restrict__ gamma,
         const float* __restrict__ beta,
         int mode,
         __half* __restrict__ out_h,
         const float* __restrict__ lw,
         const float* __restrict__ lb,
         float* __restrict__ dup) {
    extern __shared__ char sm[];
    const uint32_t sb = smem_u32(sm);
    const int tid = threadIdx.x;
    const int lane = tid & 31;
    const int wid = tid >> 5;
    const int wm = wid & 1;          // m half: rows wm*32..+31
    const int wn = wid >> 1;         // n quarter: cols wn*64..+63
    const int row0 = blockIdx.x * 64;
    const int l0 = row0 & 511;

    float* s_bias = (float*)(sm + S_PAR);
    float* s_g = (float*)(sm + S_PAR + 1024);
    float* s_be = (float*)(sm + S_PAR + 2048);
    float* s_lw = (float*)(sm + S_PAR + 3072);
    s_bias[tid] = bias[tid];
    s_g[tid] = gamma[tid];
    s_be[tid] = beta[tid];
    s_lw[tid] = (mode == 1) ? lw[tid] : 0.f;

    // -------- B staging (cp.async), buf = st % 3 --------
    auto stage = [&](int st) {
        int kc = st, buf = st % 3;
        uint32_t sB = sb + S_B0 + (uint32_t)buf * BSZ;
        const __half* bbase = b_w + (size_t)kc * 24576;
#pragma unroll
        for (int i = 0; i < 12; i++) {
            int u = i * 256 + tid;
            int f = u / 12, rem = u % 12;
            int tap = rem >> 2, c = rem & 3;
            cp16(sB + (uint32_t)(f * 208 + tap * 64 + c * 16), bbase + u * 8, 1);
        }
        cp_commit();
    };

    // -------- load resident A tile (66 rows x 512B), then stage(0) in G0 ----
    {
        for (int idx = tid; idx < 66 * 32; idx += 256) {
            int r = idx >> 5, c = idx & 31;
            int l = l0 - 1 + r;
            int v = ((unsigned)l < 512u) ? 1 : 0;
            long grow = (long)row0 - 1 + r;
            const __half* src = a_in + (v ? (grow * 256 + c * 8) : 0);
            cp16(sb + S_A + (uint32_t)(r * A_STR + c * 16), src, v);
        }
    }
    stage(0);   // commits group G0 = {A, B stage 0}
    stage(1);   // G1

    // per-lane ldmatrix base offsets (bytes)
    const uint32_t aL = sb + S_A +
        (uint32_t)((wm * 32 + (lane & 15)) * A_STR + (lane >> 4) * 16);
    const uint32_t bL = (uint32_t)((wn * 64 + (lane & 7) + ((lane >> 4) << 3)) * 208 +
                                   ((lane >> 3) & 1) * 16);

    float d[2][8][4];
#pragma unroll
    for (int tm = 0; tm < 2; tm++)
#pragma unroll
        for (int tn = 0; tn < 8; tn++)
#pragma unroll
            for (int j = 0; j < 4; j++) d[tm][tn][j] = 0.f;

    uint32_t aF[2][2][4];    // [slot][tm][4]
    uint32_t bF[2][8][2];    // [slot][tn][2]

    for (int st = 0; st < 8; st++) {
        if (st < 7) cp_wait1(); else cp_wait0();
        __syncthreads();
        if (st + 2 < 8) stage(st + 2);

        const uint32_t Aoff = (uint32_t)(st * 64);   // col offset bytes (kc=st)
        const uint32_t Bb = sb + S_B0 + (uint32_t)(st % 3) * BSZ;

        // prefetch step 0 (tap=0, ko=0) into slot 0
        {
#pragma unroll
            for (int tm = 0; tm < 2; tm++)
                ldsm4(aF[0][tm], aL + Aoff + (uint32_t)(tm * 16 * A_STR));
#pragma unroll
            for (int g = 0; g < 4; g++) {
                uint32_t r[4];
                ldsm4(r, Bb + bL + (uint32_t)(g * 3328));
                bF[0][2 * g][0] = r[0];
                bF[0][2 * g][1] = r[1];
                bF[0][2 * g + 1][0] = r[2];
                bF[0][2 * g + 1][1] = r[3];
            }
        }

        // 6 steps: s = tap*2 + ko; prefetch s+1 while mma on s
#pragma unroll
        for (int s = 0; s < 6; s++) {
            const int cs_ = s & 1;
            const int ns_ = (s + 1) & 1;
            if (s < 5) {
                const int tap = (s + 1) >> 1, ko = (s + 1) & 1;
#pragma unroll
                for (int tm = 0; tm < 2; tm++)
                    ldsm4(aF[ns_][tm],
                          aL + Aoff +
                          (uint32_t)((tm * 16 + tap) * A_STR + ko * 32));
#pragma unroll
                for (int g = 0; g < 4; g++) {
                    uint32_t r[4];
                    ldsm4(r, Bb + bL + (uint32_t)(g * 3328 + tap * 64 + ko * 32));
                    bF[ns_][2 * g][0] = r[0];
                    bF[ns_][2 * g][1] = r[1];
                    bF[ns_][2 * g + 1][0] = r[2];
                    bF[ns_][2 * g + 1][1] = r[3];
                }
            }
#pragma unroll
            for (int tm = 0; tm < 2; tm++)
#pragma unroll
                for (int tn = 0; tn < 8; tn++)
                    mma16816(d[tm][tn], aF[cs_][tm], bF[cs_][tn]);
        }
    }

    __syncthreads();   // all warps done reading buffers before stats reuse

    // -------- epilogue: accums -> smem stats, LN per row --------
    float* stats = (float*)(sm + S_B0);       // 64 x 264 fp32 (reuses B buffers)
#pragma unroll
    for (int tm = 0; tm < 2; tm++) {
#pragma unroll
        for (int tn = 0; tn < 8; tn++) {
            int m = wm * 32 + tm * 16 + (lane >> 2);
            int n = wn * 64 + tn * 8 + (lane & 3) * 2;
            stats[m * 264 + n] = d[tm][tn][0] + s_bias[n];
            stats[m * 264 + n + 1] = d[tm][tn][1] + s_bias[n + 1];
            stats[(m + 8) * 264 + n] = d[tm][tn][2] + s_bias[n];
            stats[(m + 8) * 264 + n + 1] = d[tm][tn][3] + s_bias[n + 1];
        }
    }
    __syncthreads();

    const int row = tid >> 2, q = tid & 3;
    const float* rp = stats + row * 264 + q * 64;
    float sum = 0.f, ssq = 0.f;
#pragma unroll 8
    for (int i = 0; i < 64; i++) {
        float v = rp[i];
        sum += v;
        ssq = fmaf(v, v, ssq);
    }
    sum += __shfl_xor_sync(0xffffffffu, sum, 1);
    ssq += __shfl_xor_sync(0xffffffffu, ssq, 1);
    sum += __shfl_xor_sync(0xffffffffu, sum, 2);
    ssq += __shfl_xor_sync(0xffffffffu, ssq, 2);
    float mu = sum * (1.f / 256.f);
    float rs = rsqrtf(ssq * (1.f / 256.f) - mu * mu + EPSV);

    if (mode == 1) {
        float dot = 0.f;
#pragma unroll 8
        for (int i = 0; i < 64; i++) {
            int c = q * 64 + i;
            float y = fmaxf((rp[i] - mu) * rs * s_g[c] + s_be[c], 0.f);
            dot = fmaf(y, s_lw[c], dot);
        }
        dot += __shfl_xor_sync(0xffffffffu, dot, 1);
        dot += __shfl_xor_sync(0xffffffffu, dot, 2);
        if (q == 0) dup[row0 + row] = fmaxf(dot + lb[0], 0.f);
    } else {
        // 8 x (8 fp16) vector stores per thread
#pragma unroll
        for (int v8 = 0; v8 < 8; v8++) {
            __half h[8];
#pragma unroll
            for (int j = 0; j < 8; j++) {
                int c = q * 64 + v8 * 8 + j;
                float y = fmaxf((rp[v8 * 8 + j] - mu) * rs * s_g[c] + s_be[c], 0.f);
                h[j] = __float2half(y);
            }
            size_t go = (size_t)(row0 + row) * 256 + q * 64 + v8 * 8;
            *(uint4*)(out_h + go) = *(uint4*)h;
        }
    }
}

// ---------------------------------------------------------------------------
extern "C" void kernel_launch(void* const* d_in, const int* in_sizes, int n_in,
                              void* d_out, int out_size) {
    const float* x      = (const float*)d_in[0];
    const int*   target = (const int*)d_in[1];
    const float* w1  = (const float*)d_in[3];
    const float* b1  = (const float*)d_in[4];
    const float* g1  = (const float*)d_in[5];
    const float* be1 = (const float*)d_in[6];
    const float* w2  = (const float*)d_in[7];
    const float* b2  = (const float*)d_in[8];
    const float* g2  = (const float*)d_in[9];
    const float* be2 = (const float*)d_in[10];
    const float* lw  = (const float*)d_in[11];
    const float* lb  = (const float*)d_in[12];

    float* out = (float*)d_out;
    float* dup = out + (size_t)BB * MM * DD;

    __half *xh, *h1h, *B1, *B2;
    int* cs;
    cudaGetSymbolAddress((void**)&xh, g_xh);
    cudaGetSymbolAddress((void**)&h1h, g_h1h);
    cudaGetSymbolAddress((void**)&B1, g_B1);
    cudaGetSymbolAddress((void**)&B2, g_B2);
    cudaGetSymbolAddress((void**)&cs, g_cs);

    cudaFuncSetAttribute((const void*)conv_mma,
                         cudaFuncAttributeMaxDynamicSharedMemorySize, S_TOTAL);

    prep_convert<<<(BB * LL * DD / 4 + 255) / 256, 256>>>(x, w1, w2);
    cumsum_k<<<BB, LL>>>(target, cs);
    regulate<<<BB * MM / 8, 256>>>(x, cs, out);

    conv_mma<<<BB * LL / 64, 256, S_TOTAL>>>(xh, B1, b1, g1, be1, 0,
                                             h1h, lw, lb, dup);
    conv_mma<<<BB * LL / 64, 256, S_TOTAL>>>(h1h, B2, b2, g2, be2, 1,
                                             h1h, lw, lb, dup);
}

// round 10
// speedup vs baseline: 2.2713x; 1.0503x over previous
#include <cuda_runtime.h>
#include <cuda_fp16.h>
#include <cstdint>

#define BB 16
#define LL 512
#define DD 256
#define FF 256
#define MM 2048
#define EPSV 1e-5f

// ---------------- device scratch ----------------
__device__ __align__(16) __half g_xh[BB * LL * DD];     // x in fp16
__device__ __align__(16) __half g_h1h[BB * LL * FF];    // conv1 output in fp16
// weights in mma-FRAGMENT order: uint4 index = (ks*16 + p)*32 + lane,
// ks = kc*6 + tap*2 + ko (48 k-steps), p = n-16-group (16), lane (32).
// uint4 = {b0(n=p*16+l/4), b1(same n,k+8), b0(n+8), b1(n+8)}
__device__ __align__(16) uint4 g_B1f[48 * 16 * 32];
__device__ __align__(16) uint4 g_B2f[48 * 16 * 32];
__device__ int g_cs[BB * LL];

// ---------------- helpers ----------------
__device__ __forceinline__ uint32_t smem_u32(const void* p) {
    uint32_t a;
    asm("{ .reg .u64 t; cvta.to.shared.u64 t, %1; cvt.u32.u64 %0, t; }"
        : "=r"(a) : "l"(p));
    return a;
}

__device__ __forceinline__ void cp16(uint32_t dst, const void* src, int valid) {
    int sz = valid ? 16 : 0;
    asm volatile("cp.async.cg.shared.global [%0], [%1], %2, %3;"
                 :: "r"(dst), "l"(src), "n"(16), "r"(sz));
}
__device__ __forceinline__ void cp_commit() {
    asm volatile("cp.async.commit_group;" ::: "memory");
}
__device__ __forceinline__ void cp_wait0() {
    asm volatile("cp.async.wait_group 0;" ::: "memory");
}

__device__ __forceinline__ void ldsm4(uint32_t* r, uint32_t addr) {
    asm volatile("ldmatrix.sync.aligned.m8n8.x4.shared.b16 {%0,%1,%2,%3}, [%4];"
                 : "=r"(r[0]), "=r"(r[1]), "=r"(r[2]), "=r"(r[3]) : "r"(addr));
}

__device__ __forceinline__ void ldg128(uint4& v, const uint4* p) {
    asm volatile("ld.global.nc.v4.u32 {%0,%1,%2,%3}, [%4];"
                 : "=r"(v.x), "=r"(v.y), "=r"(v.z), "=r"(v.w) : "l"(p));
}

__device__ __forceinline__ void mma16816(float* d, const uint32_t* a,
                                         const uint32_t* b) {
    asm volatile(
        "mma.sync.aligned.m16n8k16.row.col.f32.f16.f16.f32 "
        "{%0,%1,%2,%3}, {%4,%5,%6,%7}, {%8,%9}, {%0,%1,%2,%3};"
        : "+f"(d[0]), "+f"(d[1]), "+f"(d[2]), "+f"(d[3])
        : "r"(a[0]), "r"(a[1]), "r"(a[2]), "r"(a[3]), "r"(b[0]), "r"(b[1]));
}

// ---------------- prep: x -> fp16; weights -> fragment-order fp16 ----------
__global__ void prep_convert(const float* __restrict__ x,
                             const float* __restrict__ w1,
                             const float* __restrict__ w2) {
    int i4 = blockIdx.x * 256 + threadIdx.x;   // vec4 index
    if (i4 < BB * LL * DD / 4) {
        float4 v = reinterpret_cast<const float4*>(x)[i4];
        __half h[4];
        h[0] = __float2half(v.x);
        h[1] = __float2half(v.y);
        h[2] = __float2half(v.z);
        h[3] = __float2half(v.w);
        reinterpret_cast<uint2*>(g_xh)[i4] = *(uint2*)h;
    }
    if (i4 < 48 * 16 * 32) {
        int lane = i4 & 31;
        int rest = i4 >> 5;
        int p = rest & 15;
        int ks = rest >> 4;          // 0..47
        int kc = ks / 6, s = ks % 6;
        int tap = s >> 1, ko = s & 1;
        int l4 = lane & 3, lq = lane >> 2;
        int d0 = kc * 32 + ko * 16 + l4 * 2;
        int na = p * 16 + lq, nb = na + 8;
        // pack two consecutive-d weights into one u32 (half2)
        auto pack = [&](const float* w, int n, int d) -> unsigned {
            __half2 h = __floats2half2_rn(w[n * 768 + d * 3 + tap],
                                          w[n * 768 + (d + 1) * 3 + tap]);
            return *(unsigned*)&h;
        };
        uint4 v1, v2;
        v1.x = pack(w1, na, d0);
        v1.y = pack(w1, na, d0 + 8);
        v1.z = pack(w1, nb, d0);
        v1.w = pack(w1, nb, d0 + 8);
        v2.x = pack(w2, na, d0);
        v2.y = pack(w2, na, d0 + 8);
        v2.z = pack(w2, nb, d0);
        v2.w = pack(w2, nb, d0 + 8);
        g_B1f[i4] = v1;
        g_B2f[i4] = v2;
    }
}

// ---------------- cumsum ----------------
__global__ void cumsum_k(const int* __restrict__ t, int* __restrict__ cs) {
    __shared__ int s[LL];
    int b = blockIdx.x, tid = threadIdx.x;
    s[tid] = t[(b << 9) + tid];
    __syncthreads();
    for (int off = 1; off < LL; off <<= 1) {
        int v = (tid >= off) ? s[tid - off] : 0;
        __syncthreads();
        s[tid] += v;
        __syncthreads();
    }
    cs[(b << 9) + tid] = s[tid];
}

// ---------------- length regulate (exact) ----------------
__global__ void regulate(const float* __restrict__ x,
                         const int* __restrict__ cs,
                         float* __restrict__ out) {
    int warp = threadIdx.x >> 5, lane = threadIdx.x & 31;
    int gm = blockIdx.x * 8 + warp;
    int b = gm >> 11;
    int m = gm & (MM - 1);
    const int* c = cs + (b << 9);
    int total = c[LL - 1];
    float4* dst = reinterpret_cast<float4*>(out) + (size_t)gm * 64;
    if (m < total) {
        int lo = 0, hi = LL - 1;
        while (lo < hi) {
            int mid = (lo + hi) >> 1;
            if (c[mid] > m) hi = mid; else lo = mid + 1;
        }
        const float4* src =
            reinterpret_cast<const float4*>(x) + ((size_t)((b << 9) + lo)) * 64;
        dst[lane] = src[lane];
        dst[lane + 32] = src[lane + 32];
    } else {
        float4 z = make_float4(0.f, 0.f, 0.f, 0.f);
        dst[lane] = z;
        dst[lane + 32] = z;
    }
}

// ---------------- fp16 conv(K=3): A smem-resident, B direct-LDG fragments --
// CTA: 64 rows x 256 channels; 8 warps (2m x 4n), warp tile 32x64.
// Zero barriers in the k-loop; B ring-buffered in regs (distance 2).
#define S_PAR   0                  // bias/g/be/lw: 4 x 1KB
#define S_A     4096
#define A_STR   528
#define ASZ_R   (66 * A_STR)       // 34848
#define STATS_B (64 * 264 * 4)     // 67584 (overlaps A region)
#define S_TOTAL (4096 + STATS_B)   // 71680

__global__ void __launch_bounds__(256, 1)
conv_mma(const __half* __restrict__ a_in,
         const uint4* __restrict__ Bf,
         const float* __restrict__ bias,
         const float* __restrict__ gamma,
         const float* __restrict__ beta,
         int mode,
         __half* __restrict__ out_h,
         const float* __restrict__ lw,
         const float* __restrict__ lb,
         float* __restrict__ dup) {
    extern __shared__ char sm[];
    const uint32_t sb = smem_u32(sm);
    const int tid = threadIdx.x;
    const int lane = tid & 31;
    const int wid = tid >> 5;
    const int wm = wid & 1;
    const int wn = wid >> 1;
    const int row0 = blockIdx.x * 64;
    const int l0 = row0 & 511;

    float* s_bias = (float*)(sm + S_PAR);
    float* s_g = (float*)(sm + S_PAR + 1024);
    float* s_be = (float*)(sm + S_PAR + 2048);
    float* s_lw = (float*)(sm + S_PAR + 3072);
    s_bias[tid] = bias[tid];
    s_g[tid] = gamma[tid];
    s_be[tid] = beta[tid];
    s_lw[tid] = (mode == 1) ? lw[tid] : 0.f;

    // resident A tile (66 rows x 512B) via cp.async
    for (int idx = tid; idx < 66 * 32; idx += 256) {
        int r = idx >> 5, c = idx & 31;
        int l = l0 - 1 + r;
        int v = ((unsigned)l < 512u) ? 1 : 0;
        long grow = (long)row0 - 1 + r;
        const __half* src = a_in + (v ? (grow * 256 + c * 8) : 0);
        cp16(sb + S_A + (uint32_t)(r * A_STR + c * 16), src, v);
    }
    cp_commit();

    // per-warp B fragment pointer: idx4 = (ks*16 + wn*4 + g)*32 + lane
    const uint4* Bw = Bf + (size_t)(wn * 4) * 32 + lane;

    // B prefetch ring (3 slots, distance 2)
    uint4 bS[3][4];
#pragma unroll
    for (int g = 0; g < 4; g++) ldg128(bS[0][g], Bw + g * 32);
#pragma unroll
    for (int g = 0; g < 4; g++) ldg128(bS[1][g], Bw + 512 + g * 32);

    cp_wait0();
    __syncthreads();

    const uint32_t aL = sb + S_A +
        (uint32_t)((wm * 32 + (lane & 15)) * A_STR + (lane >> 4) * 16);

    float d[2][8][4];
#pragma unroll
    for (int tm = 0; tm < 2; tm++)
#pragma unroll
        for (int tn = 0; tn < 8; tn++)
#pragma unroll
            for (int j = 0; j < 4; j++) d[tm][tn][j] = 0.f;

    uint32_t aF[2][2][4];
    // A ldsm for ks = 0 (kc=0, tap=0, ko=0)
#pragma unroll
    for (int tm = 0; tm < 2; tm++)
        ldsm4(aF[0][tm], aL + (uint32_t)(tm * 16 * A_STR));

    for (int kc = 0; kc < 8; kc++) {
#pragma unroll
        for (int s = 0; s < 6; s++) {
            const int ks = kc * 6 + s;
            // B prefetch ks+2
            if (ks + 2 < 48) {
                const uint4* bp = Bw + (size_t)(ks + 2) * 512;
#pragma unroll
                for (int g = 0; g < 4; g++)
                    ldg128(bS[(s + 2) % 3][g], bp + g * 32);
            }
            // A prefetch ks+1
            if (ks + 1 < 48) {
                const int kn = (ks + 1) / 6, sn = (ks + 1) % 6;
                const int tap = sn >> 1, ko = sn & 1;
#pragma unroll
                for (int tm = 0; tm < 2; tm++)
                    ldsm4(aF[(s + 1) & 1][tm],
                          aL + (uint32_t)(kn * 64 + (tm * 16 + tap) * A_STR +
                                          ko * 32));
            }
            // mma on slot s%3, A slot s&1
            const int sl = s % 3, ca = s & 1;
#pragma unroll
            for (int tm = 0; tm < 2; tm++)
#pragma unroll
                for (int g = 0; g < 4; g++) {
                    const uint32_t* bb = (const uint32_t*)&bS[sl][g];
                    mma16816(d[tm][2 * g], aF[ca][tm], bb);
                    mma16816(d[tm][2 * g + 1], aF[ca][tm], bb + 2);
                }
        }
    }

    __syncthreads();   // A region about to be reused as stats

    // -------- epilogue: accums -> smem stats, LN per row --------
    float* stats = (float*)(sm + S_A);       // 64 x 264 fp32
#pragma unroll
    for (int tm = 0; tm < 2; tm++) {
#pragma unroll
        for (int tn = 0; tn < 8; tn++) {
            int m = wm * 32 + tm * 16 + (lane >> 2);
            int n = wn * 64 + tn * 8 + (lane & 3) * 2;
            stats[m * 264 + n] = d[tm][tn][0] + s_bias[n];
            stats[m * 264 + n + 1] = d[tm][tn][1] + s_bias[n + 1];
            stats[(m + 8) * 264 + n] = d[tm][tn][2] + s_bias[n];
            stats[(m + 8) * 264 + n + 1] = d[tm][tn][3] + s_bias[n + 1];
        }
    }
    __syncthreads();

    const int row = tid >> 2, q = tid & 3;
    const float* rp = stats + row * 264 + q * 64;
    float sum = 0.f, ssq = 0.f;
#pragma unroll 8
    for (int i = 0; i < 64; i++) {
        float v = rp[i];
        sum += v;
        ssq = fmaf(v, v, ssq);
    }
    sum += __shfl_xor_sync(0xffffffffu, sum, 1);
    ssq += __shfl_xor_sync(0xffffffffu, ssq, 1);
    sum += __shfl_xor_sync(0xffffffffu, sum, 2);
    ssq += __shfl_xor_sync(0xffffffffu, ssq, 2);
    float mu = sum * (1.f / 256.f);
    float rs = rsqrtf(ssq * (1.f / 256.f) - mu * mu + EPSV);

    if (mode == 1) {
        float dot = 0.f;
#pragma unroll 8
        for (int i = 0; i < 64; i++) {
            int c = q * 64 + i;
            float y = fmaxf((rp[i] - mu) * rs * s_g[c] + s_be[c], 0.f);
            dot = fmaf(y, s_lw[c], dot);
        }
        dot += __shfl_xor_sync(0xffffffffu, dot, 1);
        dot += __shfl_xor_sync(0xffffffffu, dot, 2);
        if (q == 0) dup[row0 + row] = fmaxf(dot + lb[0], 0.f);
    } else {
#pragma unroll
        for (int v8 = 0; v8 < 8; v8++) {
            __half h[8];
#pragma unroll
            for (int j = 0; j < 8; j++) {
                int c = q * 64 + v8 * 8 + j;
                float y = fmaxf((rp[v8 * 8 + j] - mu) * rs * s_g[c] + s_be[c], 0.f);
                h[j] = __float2half(y);
            }
            size_t go = (size_t)(row0 + row) * 256 + q * 64 + v8 * 8;
            *(uint4*)(out_h + go) = *(uint4*)h;
        }
    }
}

// ---------------------------------------------------------------------------
extern "C" void kernel_launch(void* const* d_in, const int* in_sizes, int n_in,
                              void* d_out, int out_size) {
    const float* x      = (const float*)d_in[0];
    const int*   target = (const int*)d_in[1];
    const float* w1  = (const float*)d_in[3];
    const float* b1  = (const float*)d_in[4];
    const float* g1  = (const float*)d_in[5];
    const float* be1 = (const float*)d_in[6];
    const float* w2  = (const float*)d_in[7];
    const float* b2  = (const float*)d_in[8];
    const float* g2  = (const float*)d_in[9];
    const float* be2 = (const float*)d_in[10];
    const float* lw  = (const float*)d_in[11];
    const float* lb  = (const float*)d_in[12];

    float* out = (float*)d_out;
    float* dup = out + (size_t)BB * MM * DD;

    __half *xh, *h1h;
    uint4 *B1f, *B2f;
    int* cs;
    cudaGetSymbolAddress((void**)&xh, g_xh);
    cudaGetSymbolAddress((void**)&h1h, g_h1h);
    cudaGetSymbolAddress((void**)&B1f, g_B1f);
    cudaGetSymbolAddress((void**)&B2f, g_B2f);
    cudaGetSymbolAddress((void**)&cs, g_cs);

    cudaFuncSetAttribute((const void*)conv_mma,
                         cudaFuncAttributeMaxDynamicSharedMemorySize, S_TOTAL);

    prep_convert<<<(BB * LL * DD / 4 + 255) / 256, 256>>>(x, w1, w2);
    cumsum_k<<<BB, LL>>>(target, cs);
    regulate<<<BB * MM / 8, 256>>>(x, cs, out);

    conv_mma<<<BB * LL / 64, 256, S_TOTAL>>>(xh, B1f, b1, g1, be1, 0,
                                             h1h, lw, lb, dup);
    conv_mma<<<BB * LL / 64, 256, S_TOTAL>>>(h1h, B2f, b2, g2, be2, 1,
                                             h1h, lw, lb, dup);
}